// round 1
// baseline (speedup 1.0000x reference)
#include <cuda_runtime.h>
#include <math.h>

// ---------------------------------------------------------------------------
// Problem constants
// ---------------------------------------------------------------------------
#define B_   2
#define S_   2048
#define E_   2048
#define H_   16
#define KV_  4
#define D_   128
#define WIN_ 1024
#define CAPF 50.0f
#define SCALEF 0.08838834764831845f   // 1/sqrt(128)
#define BS_  (B_*S_)                   // 4096

// ---------------------------------------------------------------------------
// Scratch (static device globals; no runtime allocation allowed)
// ---------------------------------------------------------------------------
__device__ float g_q_raw[(size_t)BS_*2048];   // [B*S, H*D]
__device__ float g_k_raw[(size_t)BS_*512];    // [B*S, KV*D]
__device__ float g_v_raw[(size_t)BS_*512];
__device__ float g_qt[(size_t)BS_*2048];      // [B,H,S,D]
__device__ float g_kt[(size_t)BS_*512];       // [B,KV,S,D]
__device__ float g_vt[(size_t)BS_*512];       // [B,KV,S,D]
__device__ float g_ctx[(size_t)BS_*2048];     // [B*S, H*D]

// ---------------------------------------------------------------------------
// Classic fp32 SGEMM: C[M,N] = A[M,K] @ B[K,N], all row-major.
// 128x128 tile, BK=8, 256 threads, 8x8 per thread. M,N,K multiples of 128/8.
// ---------------------------------------------------------------------------
__global__ __launch_bounds__(256, 2)
void sgemm128(const float* __restrict__ A, const float* __restrict__ B,
              float* __restrict__ C, int N, int K) {
    __shared__ float As[8][128];   // transposed A tile: As[k][m]
    __shared__ float Bs[8][128];   // Bs[k][n]
    const int tid = threadIdx.x;
    const int tx = tid & 15, ty = tid >> 4;
    const float* Ap = A + (size_t)blockIdx.y * 128 * K;
    const float* Bp = B + blockIdx.x * 128;
    const int aRow = tid >> 1, aCol = (tid & 1) * 4;
    const int bRow = tid >> 5, bCol = (tid & 31) * 4;

    float acc[8][8];
#pragma unroll
    for (int i = 0; i < 8; ++i)
#pragma unroll
        for (int j = 0; j < 8; ++j) acc[i][j] = 0.f;

    for (int k0 = 0; k0 < K; k0 += 8) {
        float4 av = *(const float4*)(Ap + (size_t)aRow * K + k0 + aCol);
        As[aCol + 0][aRow] = av.x;
        As[aCol + 1][aRow] = av.y;
        As[aCol + 2][aRow] = av.z;
        As[aCol + 3][aRow] = av.w;
        *(float4*)&Bs[bRow][bCol] =
            *(const float4*)(Bp + (size_t)(k0 + bRow) * N + bCol);
        __syncthreads();
#pragma unroll
        for (int k = 0; k < 8; ++k) {
            float ra[8], rb[8];
            *(float4*)(ra)     = *(const float4*)&As[k][ty * 8];
            *(float4*)(ra + 4) = *(const float4*)&As[k][ty * 8 + 4];
            *(float4*)(rb)     = *(const float4*)&Bs[k][tx * 8];
            *(float4*)(rb + 4) = *(const float4*)&Bs[k][tx * 8 + 4];
#pragma unroll
            for (int i = 0; i < 8; ++i)
#pragma unroll
                for (int j = 0; j < 8; ++j)
                    acc[i][j] = fmaf(ra[i], rb[j], acc[i][j]);
        }
        __syncthreads();
    }
    float* Cp = C + (size_t)(blockIdx.y * 128 + ty * 8) * N + blockIdx.x * 128 + tx * 8;
#pragma unroll
    for (int i = 0; i < 8; ++i) {
        *(float4*)(Cp + (size_t)i * N) =
            make_float4(acc[i][0], acc[i][1], acc[i][2], acc[i][3]);
        *(float4*)(Cp + (size_t)i * N + 4) =
            make_float4(acc[i][4], acc[i][5], acc[i][6], acc[i][7]);
    }
}

// ---------------------------------------------------------------------------
// RMSNorm + RoPE + transpose to [B, nH, S, D].
// grid.x = B*S, grid.y = 24 slots (0..15: Q heads, 16..19: K heads, 20..23: V copy)
// 128 threads per block (one per d).
// ---------------------------------------------------------------------------
__global__ void normrope_kernel(const int* __restrict__ positions,
                                const float* __restrict__ qscale,
                                const float* __restrict__ kscale) {
    const int bs = blockIdx.x, slot = blockIdx.y, t = threadIdx.x;
    const int b = bs >> 11, s = bs & (S_ - 1);

    if (slot >= 20) {  // V: pure transpose copy
        int kvh = slot - 20;
        g_vt[((size_t)(b * KV_ + kvh) * S_ + s) * D_ + t] =
            g_v_raw[(size_t)bs * 512 + kvh * 128 + t];
        return;
    }

    const float* in;
    float* out;
    const float* scale;
    if (slot < 16) {
        in = g_q_raw + (size_t)bs * 2048 + slot * 128;
        out = g_qt + ((size_t)(b * H_ + slot) * S_ + s) * D_;
        scale = qscale;
    } else {
        int kvh = slot - 16;
        in = g_k_raw + (size_t)bs * 512 + kvh * 128;
        out = g_kt + ((size_t)(b * KV_ + kvh) * S_ + s) * D_;
        scale = kscale;
    }

    float x = in[t];
    float ss = x * x;
#pragma unroll
    for (int o = 16; o; o >>= 1) ss += __shfl_xor_sync(~0u, ss, o);
    __shared__ float wsum[4];
    __shared__ float sv[128];
    if ((t & 31) == 0) wsum[t >> 5] = ss;
    __syncthreads();
    ss = wsum[0] + wsum[1] + wsum[2] + wsum[3];
    float y = x * rsqrtf(ss * (1.0f / 128.0f) + 1e-6f) * scale[t];
    sv[t] = y;
    __syncthreads();

    const int pos = positions[bs];
    const int i = t & 63;
    // inv_freq = 10000^(-i/64); ln(10000)=9.210340371976184
    double ang = (double)pos * exp(-(double)i * (9.210340371976184 / 64.0));
    double sn, cs;
    sincos(ang, &sn, &cs);
    float cf = (float)cs, sf = (float)sn;
    float o;
    if (t < 64) o = y * cf - sv[t + 64] * sf;
    else        o = y * cf + sv[t - 64] * sf;
    out[t] = o;
}

// ---------------------------------------------------------------------------
// Windowed flash attention with softcap.
// grid: (S/128, B*H), 256 threads.
// Query tile BM=128, key tile BN=64. Online softmax, fp32 throughout.
// smem: Qs[d][m] (128x132), Ks[d][n] (128x68), Vs[n][d] (64x132), Ps[n][m] (64x132)
// ---------------------------------------------------------------------------
#define ATTN_SMEM ((128*132 + 128*68 + 64*132 + 64*132) * 4)

__global__ __launch_bounds__(256, 1)
void attn_kernel(const float* __restrict__ Q, const float* __restrict__ Kt,
                 const float* __restrict__ Vt, float* __restrict__ ctx) {
    extern __shared__ float smf[];
    float* Qs = smf;              // [128][132] (d, m)
    float* Ks = Qs + 128 * 132;   // [128][68]  (d, n)
    float* Vs = Ks + 128 * 68;    // [64][132]  (n, d)
    float* Ps = Vs + 64 * 132;    // [64][132]  (n, m)

    const int tid = threadIdx.x;
    const int tx = tid & 15, ty = tid >> 4;
    const int q0 = blockIdx.x * 128;
    const int b = blockIdx.y >> 4, h = blockIdx.y & 15;
    const int kvh = h >> 2;
    const float* qb = Q + ((size_t)blockIdx.y * S_ + q0) * D_;
    const float* kb = Kt + (size_t)(b * KV_ + kvh) * S_ * D_;
    const float* vb = Vt + (size_t)(b * KV_ + kvh) * S_ * D_;

    // Load Q tile transposed + pre-scale by 1/sqrt(D)
    for (int i = tid; i < 128 * 32; i += 256) {
        int m = i >> 5, d4 = (i & 31) << 2;
        float4 v = *(const float4*)(qb + m * 128 + d4);
        Qs[(d4 + 0) * 132 + m] = v.x * SCALEF;
        Qs[(d4 + 1) * 132 + m] = v.y * SCALEF;
        Qs[(d4 + 2) * 132 + m] = v.z * SCALEF;
        Qs[(d4 + 3) * 132 + m] = v.w * SCALEF;
    }

    float acc[8][8];
    float m_i[8], l_i[8];
#pragma unroll
    for (int i = 0; i < 8; ++i) {
        m_i[i] = -1e30f;
        l_i[i] = 0.f;
#pragma unroll
        for (int c = 0; c < 8; ++c) acc[i][c] = 0.f;
    }

    int jt0 = q0 - (WIN_ - 1);
    if (jt0 < 0) jt0 = 0;
    jt0 &= ~63;

    for (int jt = jt0; jt <= q0 + 127; jt += 64) {
        __syncthreads();   // protect Ks/Vs/Ps reuse (also makes Qs visible on iter 0)
        // Load K tile transposed + V tile row-major
        for (int i = tid; i < 64 * 32; i += 256) {
            int n = i >> 5, d4 = (i & 31) << 2;
            float4 v = *(const float4*)(kb + (size_t)(jt + n) * 128 + d4);
            Ks[(d4 + 0) * 68 + n] = v.x;
            Ks[(d4 + 1) * 68 + n] = v.y;
            Ks[(d4 + 2) * 68 + n] = v.z;
            Ks[(d4 + 3) * 68 + n] = v.w;
            *(float4*)(Vs + n * 132 + d4) =
                *(const float4*)(vb + (size_t)(jt + n) * 128 + d4);
        }
        __syncthreads();

        // S = Q K^T  (each thread: 8 rows x 4 cols)
        float sreg[8][4];
#pragma unroll
        for (int i = 0; i < 8; ++i)
#pragma unroll
            for (int j = 0; j < 4; ++j) sreg[i][j] = 0.f;
#pragma unroll 8
        for (int d = 0; d < 128; ++d) {
            float ra[8], rb[4];
            *(float4*)(ra)     = *(const float4*)(Qs + d * 132 + ty * 8);
            *(float4*)(ra + 4) = *(const float4*)(Qs + d * 132 + ty * 8 + 4);
            *(float4*)(rb)     = *(const float4*)(Ks + d * 68 + tx * 4);
#pragma unroll
            for (int i = 0; i < 8; ++i)
#pragma unroll
                for (int j = 0; j < 4; ++j)
                    sreg[i][j] = fmaf(ra[i], rb[j], sreg[i][j]);
        }

        // softcap + causal/window mask + online softmax update
#pragma unroll
        for (int i = 0; i < 8; ++i) {
            const int qi = q0 + ty * 8 + i;
            float tmax = -1e30f;
#pragma unroll
            for (int j = 0; j < 4; ++j) {
                const int kj = jt + tx * 4 + j;
                const bool ok = (kj <= qi) && (qi - kj < WIN_);
                float sc = CAPF * tanhf(sreg[i][j] * (1.0f / CAPF));
                sreg[i][j] = ok ? sc : -1e30f;
                tmax = fmaxf(tmax, sreg[i][j]);
            }
#pragma unroll
            for (int o = 8; o; o >>= 1)
                tmax = fmaxf(tmax, __shfl_xor_sync(~0u, tmax, o, 16));
            const float mnew = fmaxf(m_i[i], tmax);
            const float alpha = __expf(m_i[i] - mnew);
            m_i[i] = mnew;
            float rsum = 0.f;
#pragma unroll
            for (int j = 0; j < 4; ++j) {
                float p = (sreg[i][j] > -1e29f) ? __expf(sreg[i][j] - mnew) : 0.f;
                Ps[(tx * 4 + j) * 132 + ty * 8 + i] = p;
                rsum += p;
            }
#pragma unroll
            for (int o = 8; o; o >>= 1)
                rsum += __shfl_xor_sync(~0u, rsum, o, 16);
            l_i[i] = l_i[i] * alpha + rsum;
#pragma unroll
            for (int c = 0; c < 8; ++c) acc[i][c] *= alpha;
        }
        __syncthreads();   // Ps complete

        // O += P V  (each thread: 8 rows x 8 d-cols)
#pragma unroll 8
        for (int n = 0; n < 64; ++n) {
            float ra[8], rb[8];
            *(float4*)(ra)     = *(const float4*)(Ps + n * 132 + ty * 8);
            *(float4*)(ra + 4) = *(const float4*)(Ps + n * 132 + ty * 8 + 4);
            *(float4*)(rb)     = *(const float4*)(Vs + n * 132 + tx * 8);
            *(float4*)(rb + 4) = *(const float4*)(Vs + n * 132 + tx * 8 + 4);
#pragma unroll
            for (int i = 0; i < 8; ++i)
#pragma unroll
                for (int c = 0; c < 8; ++c)
                    acc[i][c] = fmaf(ra[i], rb[c], acc[i][c]);
        }
    }

    // epilogue: normalize and write ctx[b, s, h, d]
#pragma unroll
    for (int i = 0; i < 8; ++i) {
        float inv = 1.0f / l_i[i];
        float* cp = ctx + (((size_t)(b * S_ + q0 + ty * 8 + i) * H_) + h) * D_ + tx * 8;
        *(float4*)cp =
            make_float4(acc[i][0] * inv, acc[i][1] * inv, acc[i][2] * inv, acc[i][3] * inv);
        *(float4*)(cp + 4) =
            make_float4(acc[i][4] * inv, acc[i][5] * inv, acc[i][6] * inv, acc[i][7] * inv);
    }
}

// ---------------------------------------------------------------------------
// kernel_launch
// inputs: 0:x 1:positions 2:mask(unused) 3:Wq 4:Wk 5:Wv 6:Wo 7:q_norm 8:k_norm
// ---------------------------------------------------------------------------
extern "C" void kernel_launch(void* const* d_in, const int* in_sizes, int n_in,
                              void* d_out, int out_size) {
    (void)in_sizes; (void)n_in; (void)out_size;
    const float* x   = (const float*)d_in[0];
    const int* pos   = (const int*)d_in[1];
    const float* Wq  = (const float*)d_in[3];
    const float* Wk  = (const float*)d_in[4];
    const float* Wv  = (const float*)d_in[5];
    const float* Wo  = (const float*)d_in[6];
    const float* qns = (const float*)d_in[7];
    const float* kns = (const float*)d_in[8];
    float* out = (float*)d_out;

    float *qraw, *kraw, *vraw, *qt, *kt, *vt, *ctx;
    cudaGetSymbolAddress((void**)&qraw, g_q_raw);
    cudaGetSymbolAddress((void**)&kraw, g_k_raw);
    cudaGetSymbolAddress((void**)&vraw, g_v_raw);
    cudaGetSymbolAddress((void**)&qt, g_qt);
    cudaGetSymbolAddress((void**)&kt, g_kt);
    cudaGetSymbolAddress((void**)&vt, g_vt);
    cudaGetSymbolAddress((void**)&ctx, g_ctx);

    cudaFuncSetAttribute(attn_kernel,
                         cudaFuncAttributeMaxDynamicSharedMemorySize, ATTN_SMEM);

    // QKV projections
    {
        dim3 gq(2048 / 128, BS_ / 128);
        sgemm128<<<gq, 256>>>(x, Wq, qraw, 2048, 2048);
        dim3 gk(512 / 128, BS_ / 128);
        sgemm128<<<gk, 256>>>(x, Wk, kraw, 512, 2048);
        sgemm128<<<gk, 256>>>(x, Wv, vraw, 512, 2048);
    }
    // RMSNorm + RoPE + transpose
    {
        dim3 g(BS_, 24);
        normrope_kernel<<<g, 128>>>(pos, qns, kns);
    }
    // Attention
    {
        dim3 g(S_ / 128, B_ * H_);
        attn_kernel<<<g, 256, ATTN_SMEM>>>(qt, kt, vt, ctx);
    }
    // Output projection
    {
        dim3 g(2048 / 128, BS_ / 128);
        sgemm128<<<g, 256>>>(ctx, Wo, out, 2048, 2048);
    }
}

// round 3
// speedup vs baseline: 1.9938x; 1.9938x over previous
#include <cuda_runtime.h>
#include <math.h>
#include <stdint.h>

// ---------------------------------------------------------------------------
// Problem constants
// ---------------------------------------------------------------------------
#define B_   2
#define S_   2048
#define E_   2048
#define H_   16
#define KV_  4
#define D_   128
#define WIN_ 1024
#define CAPF 50.0f
#define SCALEF 0.08838834764831845f   // 1/sqrt(128)
#define BS_  (B_*S_)                   // 4096

// ---------------------------------------------------------------------------
// Scratch (static device globals; no runtime allocation allowed)
// ---------------------------------------------------------------------------
__device__ float g_wqt[(size_t)2048*2048];    // Wq^T  [N][K]
__device__ float g_wkt[(size_t)512*2048];     // Wk^T
__device__ float g_wvt[(size_t)512*2048];     // Wv^T
__device__ float g_wot[(size_t)2048*2048];    // Wo^T  [E][HD]
__device__ float g_q_raw[(size_t)BS_*2048];   // [B*S, H*D]
__device__ float g_k_raw[(size_t)BS_*512];    // [B*S, KV*D]
__device__ float g_v_raw[(size_t)BS_*512];
__device__ float g_qt[(size_t)BS_*2048];      // [B,H,S,D]
__device__ float g_kt[(size_t)BS_*512];       // [B,KV,S,D]
__device__ float g_vt[(size_t)BS_*512];       // [B,KV,S,D]
__device__ float g_ctx[(size_t)BS_*2048];     // [B*S, H*D]

// ---------------------------------------------------------------------------
// Helpers
// ---------------------------------------------------------------------------
__device__ __forceinline__ uint32_t smem_u32(const void* p) {
    uint32_t a;
    asm("{ .reg .u64 t; cvta.to.shared.u64 t, %1; cvt.u32.u64 %0, t; }"
        : "=r"(a) : "l"(p));
    return a;
}

#define CP_ASYNC16(dst_u32, gptr) \
    asm volatile("cp.async.cg.shared.global [%0], [%1], 16;" \
                 :: "r"(dst_u32), "l"(gptr) : "memory")
#define CP_COMMIT() asm volatile("cp.async.commit_group;" ::: "memory")
#define CP_WAIT1()  asm volatile("cp.async.wait_group 1;" ::: "memory")
#define CP_WAIT0()  asm volatile("cp.async.wait_group 0;" ::: "memory")

__device__ __forceinline__ uint32_t tf32r(float v) {
    uint32_t b;
    asm("cvt.rna.tf32.f32 %0, %1;" : "=r"(b) : "f"(v));
    return b;
}

__device__ __forceinline__ void mma_tf32(float* c, const uint32_t* a,
                                         const uint32_t* b) {
    asm volatile(
        "mma.sync.aligned.m16n8k8.row.col.f32.tf32.tf32.f32 "
        "{%0,%1,%2,%3}, {%4,%5,%6,%7}, {%8,%9}, {%0,%1,%2,%3};"
        : "+f"(c[0]), "+f"(c[1]), "+f"(c[2]), "+f"(c[3])
        : "r"(a[0]), "r"(a[1]), "r"(a[2]), "r"(a[3]), "r"(b[0]), "r"(b[1]));
}

// ---------------------------------------------------------------------------
// tf32 mma.sync GEMM: C[M,N] = A[M,K] @ Bt[N,K]^T   (fp32 in/out)
// 128x128 CTA tile, K chunk 32, double-buffered cp.async.
// 8 warps: 2(m) x 4(n), warp tile 64x32.  grid (N/128, M/128), 256 thr.
// smem: 2 buffers x (A[128][36] + B[128][36]) floats = 73728 B
// ---------------------------------------------------------------------------
#define GEMM_SMEM (2 * 9216 * 4)

__global__ __launch_bounds__(256)
void sgemm_mma(const float* __restrict__ A, const float* __restrict__ Bt,
               float* __restrict__ C, int N, int K) {
    extern __shared__ float sm[];
    const int tid = threadIdx.x;
    const int lane = tid & 31, w = tid >> 5;
    const int wm = (w & 1) * 64;     // warp m offset
    const int wn = (w >> 1) * 32;    // warp n offset
    const int m0 = blockIdx.y * 128, n0 = blockIdx.x * 128;
    const uint32_t smb = smem_u32(sm);
    const int NC = K >> 5;

#define LOAD_CHUNK(c) do {                                                    \
    const int _ko = (c) * 32;                                                 \
    const uint32_t _bb = smb + ((c) & 1) * 36864u;                            \
    _Pragma("unroll")                                                         \
    for (int _j = 0; _j < 8; ++_j) {                                          \
        int _idx = tid + _j * 256;                                            \
        int _row = _idx >> 3, _seg = _idx & 7;                                \
        int _r = _row & 127;                                                  \
        const float* _g = (_row >= 128)                                       \
            ? (Bt + ((size_t)(n0 + _r) * K + _ko + _seg * 4))                 \
            : (A  + ((size_t)(m0 + _r) * K + _ko + _seg * 4));                \
        uint32_t _d = _bb + ((_row >= 128) ? 18432u : 0u)                     \
                      + (uint32_t)(_r * 144 + _seg * 16);                     \
        CP_ASYNC16(_d, _g);                                                   \
    }                                                                         \
    CP_COMMIT();                                                              \
} while (0)

    float acc[4][4][4];
#pragma unroll
    for (int i = 0; i < 4; ++i)
#pragma unroll
        for (int j = 0; j < 4; ++j)
#pragma unroll
            for (int k = 0; k < 4; ++k) acc[i][j][k] = 0.f;

    LOAD_CHUNK(0);

    for (int c = 0; c < NC; ++c) {
        if (c + 1 < NC) { LOAD_CHUNK(c + 1); CP_WAIT1(); }
        else CP_WAIT0();
        __syncthreads();

        const float* As = sm + (c & 1) * 9216;
        const float* Bs = As + 4608;
        const int rA = wm + (lane >> 2);
        const int rB = wn + (lane >> 2);
#pragma unroll
        for (int k8 = 0; k8 < 4; ++k8) {
            const int kc = k8 * 8 + (lane & 3);
            uint32_t af[4][4], bf[4][2];
#pragma unroll
            for (int t = 0; t < 4; ++t) {
                af[t][0] = tf32r(As[(rA + t * 16)     * 36 + kc]);
                af[t][1] = tf32r(As[(rA + t * 16 + 8) * 36 + kc]);
                af[t][2] = tf32r(As[(rA + t * 16)     * 36 + kc + 4]);
                af[t][3] = tf32r(As[(rA + t * 16 + 8) * 36 + kc + 4]);
            }
#pragma unroll
            for (int t = 0; t < 4; ++t) {
                bf[t][0] = tf32r(Bs[(rB + t * 8) * 36 + kc]);
                bf[t][1] = tf32r(Bs[(rB + t * 8) * 36 + kc + 4]);
            }
#pragma unroll
            for (int mt = 0; mt < 4; ++mt)
#pragma unroll
                for (int nt = 0; nt < 4; ++nt)
                    mma_tf32(acc[mt][nt], af[mt], bf[nt]);
        }
        __syncthreads();
    }

    // epilogue
#pragma unroll
    for (int mt = 0; mt < 4; ++mt)
#pragma unroll
        for (int nt = 0; nt < 4; ++nt) {
            const int row = m0 + wm + mt * 16 + (lane >> 2);
            const int col = n0 + wn + nt * 8 + (lane & 3) * 2;
            *(float2*)&C[(size_t)row * N + col] =
                make_float2(acc[mt][nt][0], acc[mt][nt][1]);
            *(float2*)&C[(size_t)(row + 8) * N + col] =
                make_float2(acc[mt][nt][2], acc[mt][nt][3]);
        }
#undef LOAD_CHUNK
}

// ---------------------------------------------------------------------------
// Transpose [R,C] -> [C,R]. grid (C/32, R/32), block (32,8)
// ---------------------------------------------------------------------------
__global__ void transpose_kernel(const float* __restrict__ in,
                                 float* __restrict__ out, int R, int C) {
    __shared__ float t[32][33];
    const int c0 = blockIdx.x * 32, r0 = blockIdx.y * 32;
#pragma unroll
    for (int i = threadIdx.y; i < 32; i += 8)
        t[i][threadIdx.x] = in[(size_t)(r0 + i) * C + c0 + threadIdx.x];
    __syncthreads();
#pragma unroll
    for (int i = threadIdx.y; i < 32; i += 8)
        out[(size_t)(c0 + i) * R + r0 + threadIdx.x] = t[threadIdx.x][i];
}

// ---------------------------------------------------------------------------
// RMSNorm + RoPE + transpose to [B, nH, S, D].
// ---------------------------------------------------------------------------
__global__ void normrope_kernel(const int* __restrict__ positions,
                                const float* __restrict__ qscale,
                                const float* __restrict__ kscale) {
    const int bs = blockIdx.x, slot = blockIdx.y, t = threadIdx.x;
    const int b = bs >> 11, s = bs & (S_ - 1);

    if (slot >= 20) {  // V: pure transpose copy
        int kvh = slot - 20;
        g_vt[((size_t)(b * KV_ + kvh) * S_ + s) * D_ + t] =
            g_v_raw[(size_t)bs * 512 + kvh * 128 + t];
        return;
    }

    const float* in;
    float* out;
    const float* scale;
    if (slot < 16) {
        in = g_q_raw + (size_t)bs * 2048 + slot * 128;
        out = g_qt + ((size_t)(b * H_ + slot) * S_ + s) * D_;
        scale = qscale;
    } else {
        int kvh = slot - 16;
        in = g_k_raw + (size_t)bs * 512 + kvh * 128;
        out = g_kt + ((size_t)(b * KV_ + kvh) * S_ + s) * D_;
        scale = kscale;
    }

    float x = in[t];
    float ss = x * x;
#pragma unroll
    for (int o = 16; o; o >>= 1) ss += __shfl_xor_sync(~0u, ss, o);
    __shared__ float wsum[4];
    __shared__ float sv[128];
    if ((t & 31) == 0) wsum[t >> 5] = ss;
    __syncthreads();
    ss = wsum[0] + wsum[1] + wsum[2] + wsum[3];
    float y = x * rsqrtf(ss * (1.0f / 128.0f) + 1e-6f) * scale[t];
    sv[t] = y;
    __syncthreads();

    const int pos = positions[bs];
    const int i = t & 63;
    double ang = (double)pos * exp(-(double)i * (9.210340371976184 / 64.0));
    double sn, cs;
    sincos(ang, &sn, &cs);
    float cf = (float)cs, sf = (float)sn;
    float o;
    if (t < 64) o = y * cf - sv[t + 64] * sf;
    else        o = y * cf + sv[t - 64] * sf;
    out[t] = o;
}

// ---------------------------------------------------------------------------
// Windowed flash attention with softcap (fp32).
// ---------------------------------------------------------------------------
#define ATTN_SMEM ((128*132 + 128*68 + 64*132 + 64*132) * 4)

__global__ __launch_bounds__(256, 1)
void attn_kernel(const float* __restrict__ Q, const float* __restrict__ Kt,
                 const float* __restrict__ Vt, float* __restrict__ ctx) {
    extern __shared__ float smf[];
    float* Qs = smf;              // [128][132] (d, m)
    float* Ks = Qs + 128 * 132;   // [128][68]  (d, n)
    float* Vs = Ks + 128 * 68;    // [64][132]  (n, d)
    float* Ps = Vs + 64 * 132;    // [64][132]  (n, m)

    const int tid = threadIdx.x;
    const int tx = tid & 15, ty = tid >> 4;
    const int q0 = blockIdx.x * 128;
    const int b = blockIdx.y >> 4, h = blockIdx.y & 15;
    const int kvh = h >> 2;
    const float* qb = Q + ((size_t)blockIdx.y * S_ + q0) * D_;
    const float* kb = Kt + (size_t)(b * KV_ + kvh) * S_ * D_;
    const float* vb = Vt + (size_t)(b * KV_ + kvh) * S_ * D_;

    for (int i = tid; i < 128 * 32; i += 256) {
        int m = i >> 5, d4 = (i & 31) << 2;
        float4 v = *(const float4*)(qb + m * 128 + d4);
        Qs[(d4 + 0) * 132 + m] = v.x * SCALEF;
        Qs[(d4 + 1) * 132 + m] = v.y * SCALEF;
        Qs[(d4 + 2) * 132 + m] = v.z * SCALEF;
        Qs[(d4 + 3) * 132 + m] = v.w * SCALEF;
    }

    float acc[8][8];
    float m_i[8], l_i[8];
#pragma unroll
    for (int i = 0; i < 8; ++i) {
        m_i[i] = -1e30f;
        l_i[i] = 0.f;
#pragma unroll
        for (int c = 0; c < 8; ++c) acc[i][c] = 0.f;
    }

    int jt0 = q0 - (WIN_ - 1);
    if (jt0 < 0) jt0 = 0;
    jt0 &= ~63;

    for (int jt = jt0; jt <= q0 + 127; jt += 64) {
        __syncthreads();
        for (int i = tid; i < 64 * 32; i += 256) {
            int n = i >> 5, d4 = (i & 31) << 2;
            float4 v = *(const float4*)(kb + (size_t)(jt + n) * 128 + d4);
            Ks[(d4 + 0) * 68 + n] = v.x;
            Ks[(d4 + 1) * 68 + n] = v.y;
            Ks[(d4 + 2) * 68 + n] = v.z;
            Ks[(d4 + 3) * 68 + n] = v.w;
            *(float4*)(Vs + n * 132 + d4) =
                *(const float4*)(vb + (size_t)(jt + n) * 128 + d4);
        }
        __syncthreads();

        float sreg[8][4];
#pragma unroll
        for (int i = 0; i < 8; ++i)
#pragma unroll
            for (int j = 0; j < 4; ++j) sreg[i][j] = 0.f;
#pragma unroll 8
        for (int d = 0; d < 128; ++d) {
            float ra[8], rb[4];
            *(float4*)(ra)     = *(const float4*)(Qs + d * 132 + ty * 8);
            *(float4*)(ra + 4) = *(const float4*)(Qs + d * 132 + ty * 8 + 4);
            *(float4*)(rb)     = *(const float4*)(Ks + d * 68 + tx * 4);
#pragma unroll
            for (int i = 0; i < 8; ++i)
#pragma unroll
                for (int j = 0; j < 4; ++j)
                    sreg[i][j] = fmaf(ra[i], rb[j], sreg[i][j]);
        }

#pragma unroll
        for (int i = 0; i < 8; ++i) {
            const int qi = q0 + ty * 8 + i;
            float tmax = -1e30f;
#pragma unroll
            for (int j = 0; j < 4; ++j) {
                const int kj = jt + tx * 4 + j;
                const bool ok = (kj <= qi) && (qi - kj < WIN_);
                float sc = CAPF * tanhf(sreg[i][j] * (1.0f / CAPF));
                sreg[i][j] = ok ? sc : -1e30f;
                tmax = fmaxf(tmax, sreg[i][j]);
            }
#pragma unroll
            for (int o = 8; o; o >>= 1)
                tmax = fmaxf(tmax, __shfl_xor_sync(~0u, tmax, o, 16));
            const float mnew = fmaxf(m_i[i], tmax);
            const float alpha = __expf(m_i[i] - mnew);
            m_i[i] = mnew;
            float rsum = 0.f;
#pragma unroll
            for (int j = 0; j < 4; ++j) {
                float p = (sreg[i][j] > -1e29f) ? __expf(sreg[i][j] - mnew) : 0.f;
                Ps[(tx * 4 + j) * 132 + ty * 8 + i] = p;
                rsum += p;
            }
#pragma unroll
            for (int o = 8; o; o >>= 1)
                rsum += __shfl_xor_sync(~0u, rsum, o, 16);
            l_i[i] = l_i[i] * alpha + rsum;
#pragma unroll
            for (int c = 0; c < 8; ++c) acc[i][c] *= alpha;
        }
        __syncthreads();

#pragma unroll 8
        for (int n = 0; n < 64; ++n) {
            float ra[8], rb[8];
            *(float4*)(ra)     = *(const float4*)(Ps + n * 132 + ty * 8);
            *(float4*)(ra + 4) = *(const float4*)(Ps + n * 132 + ty * 8 + 4);
            *(float4*)(rb)     = *(const float4*)(Vs + n * 132 + tx * 8);
            *(float4*)(rb + 4) = *(const float4*)(Vs + n * 132 + tx * 8 + 4);
#pragma unroll
            for (int i = 0; i < 8; ++i)
#pragma unroll
                for (int c = 0; c < 8; ++c)
                    acc[i][c] = fmaf(ra[i], rb[c], acc[i][c]);
        }
    }

    // epilogue: normalize and write ctx[b, s, h, d]
#pragma unroll
    for (int i = 0; i < 8; ++i) {
        float inv = 1.0f / l_i[i];
        float* cp = ctx + (((size_t)(b * S_ + q0 + ty * 8 + i) * H_) + h) * D_ + tx * 8;
        *(float4*)cp =
            make_float4(acc[i][0] * inv, acc[i][1] * inv, acc[i][2] * inv, acc[i][3] * inv);
        *(float4*)(cp + 4) =
            make_float4(acc[i][4] * inv, acc[i][5] * inv, acc[i][6] * inv, acc[i][7] * inv);
    }
}

// ---------------------------------------------------------------------------
// kernel_launch
// inputs: 0:x 1:positions 2:mask(unused) 3:Wq 4:Wk 5:Wv 6:Wo 7:q_norm 8:k_norm
// ---------------------------------------------------------------------------
extern "C" void kernel_launch(void* const* d_in, const int* in_sizes, int n_in,
                              void* d_out, int out_size) {
    (void)in_sizes; (void)n_in; (void)out_size;
    const float* x   = (const float*)d_in[0];
    const int* pos   = (const int*)d_in[1];
    const float* Wq  = (const float*)d_in[3];
    const float* Wk  = (const float*)d_in[4];
    const float* Wv  = (const float*)d_in[5];
    const float* Wo  = (const float*)d_in[6];
    const float* qns = (const float*)d_in[7];
    const float* kns = (const float*)d_in[8];
    float* out = (float*)d_out;

    float *wqt, *wkt, *wvt, *wot;
    float *qraw, *kraw, *vraw, *qt, *kt, *vt, *ctx;
    cudaGetSymbolAddress((void**)&wqt, g_wqt);
    cudaGetSymbolAddress((void**)&wkt, g_wkt);
    cudaGetSymbolAddress((void**)&wvt, g_wvt);
    cudaGetSymbolAddress((void**)&wot, g_wot);
    cudaGetSymbolAddress((void**)&qraw, g_q_raw);
    cudaGetSymbolAddress((void**)&kraw, g_k_raw);
    cudaGetSymbolAddress((void**)&vraw, g_v_raw);
    cudaGetSymbolAddress((void**)&qt, g_qt);
    cudaGetSymbolAddress((void**)&kt, g_kt);
    cudaGetSymbolAddress((void**)&vt, g_vt);
    cudaGetSymbolAddress((void**)&ctx, g_ctx);

    cudaFuncSetAttribute(attn_kernel,
                         cudaFuncAttributeMaxDynamicSharedMemorySize, ATTN_SMEM);
    cudaFuncSetAttribute(sgemm_mma,
                         cudaFuncAttributeMaxDynamicSharedMemorySize, GEMM_SMEM);

    // 1. transpose weights to [N,K]
    {
        dim3 blk(32, 8);
        transpose_kernel<<<dim3(2048 / 32, 2048 / 32), blk>>>(Wq, wqt, 2048, 2048);
        transpose_kernel<<<dim3(512 / 32, 2048 / 32), blk>>>(Wk, wkt, 2048, 512);
        transpose_kernel<<<dim3(512 / 32, 2048 / 32), blk>>>(Wv, wvt, 2048, 512);
        transpose_kernel<<<dim3(2048 / 32, 2048 / 32), blk>>>(Wo, wot, 2048, 2048);
    }
    // 2. QKV projections (tf32 mma.sync)
    {
        sgemm_mma<<<dim3(2048 / 128, BS_ / 128), 256, GEMM_SMEM>>>(x, wqt, qraw, 2048, 2048);
        sgemm_mma<<<dim3(512 / 128, BS_ / 128), 256, GEMM_SMEM>>>(x, wkt, kraw, 512, 2048);
        sgemm_mma<<<dim3(512 / 128, BS_ / 128), 256, GEMM_SMEM>>>(x, wvt, vraw, 512, 2048);
    }
    // 3. RMSNorm + RoPE + transpose
    {
        dim3 g(BS_, 24);
        normrope_kernel<<<g, 128>>>(pos, qns, kns);
    }
    // 4. Attention
    {
        dim3 g(S_ / 128, B_ * H_);
        attn_kernel<<<g, 256, ATTN_SMEM>>>(qt, kt, vt, ctx);
    }
    // 5. Output projection
    {
        sgemm_mma<<<dim3(2048 / 128, BS_ / 128), 256, GEMM_SMEM>>>(ctx, wot, out, 2048, 2048);
    }
}

// round 4
// speedup vs baseline: 3.3021x; 1.6562x over previous
#include <cuda_runtime.h>
#include <cuda_fp16.h>
#include <math.h>
#include <stdint.h>

// ---------------------------------------------------------------------------
// Problem constants
// ---------------------------------------------------------------------------
#define B_   2
#define S_   2048
#define E_   2048
#define H_   16
#define KV_  4
#define D_   128
#define WIN_ 1024
#define SCALEF 0.08838834764831845f   // 1/sqrt(128)
#define BS_  (B_*S_)                   // 4096

// ---------------------------------------------------------------------------
// Scratch (static device globals; no runtime allocation allowed)
// ---------------------------------------------------------------------------
__device__ float g_wqt[(size_t)2048*2048];    // Wq^T  [N][K]
__device__ float g_wkt[(size_t)512*2048];     // Wk^T
__device__ float g_wvt[(size_t)512*2048];     // Wv^T
__device__ float g_wot[(size_t)2048*2048];    // Wo^T  [E][HD]
__device__ float g_q_raw[(size_t)BS_*2048];   // [B*S, H*D]
__device__ float g_k_raw[(size_t)BS_*512];    // [B*S, KV*D]
__device__ float g_v_raw[(size_t)BS_*512];
__device__ __half g_qh[(size_t)BS_*2048];     // [B,H,S,D] fp16 hi (scaled)
__device__ __half g_ql[(size_t)BS_*2048];     // fp16 lo residual
__device__ __half g_kh[(size_t)BS_*512];      // [B,KV,S,D] fp16
__device__ __half g_vh[(size_t)BS_*512];      // [B,KV,S,D] fp16
__device__ float g_ctx[(size_t)BS_*2048];     // [B*S, H*D]

// ---------------------------------------------------------------------------
// Helpers
// ---------------------------------------------------------------------------
__device__ __forceinline__ uint32_t smem_u32(const void* p) {
    uint32_t a;
    asm("{ .reg .u64 t; cvta.to.shared.u64 t, %1; cvt.u32.u64 %0, t; }"
        : "=r"(a) : "l"(p));
    return a;
}

#define CP_ASYNC16(dst_u32, gptr) \
    asm volatile("cp.async.cg.shared.global [%0], [%1], 16;" \
                 :: "r"(dst_u32), "l"(gptr) : "memory")
#define CP_COMMIT() asm volatile("cp.async.commit_group;" ::: "memory")
#define CP_WAIT1()  asm volatile("cp.async.wait_group 1;" ::: "memory")
#define CP_WAIT0()  asm volatile("cp.async.wait_group 0;" ::: "memory")

__device__ __forceinline__ uint32_t tf32r(float v) {
    uint32_t b;
    asm("cvt.rna.tf32.f32 %0, %1;" : "=r"(b) : "f"(v));
    return b;
}

__device__ __forceinline__ void mma_tf32(float* c, const uint32_t* a,
                                         const uint32_t* b) {
    asm volatile(
        "mma.sync.aligned.m16n8k8.row.col.f32.tf32.tf32.f32 "
        "{%0,%1,%2,%3}, {%4,%5,%6,%7}, {%8,%9}, {%0,%1,%2,%3};"
        : "+f"(c[0]), "+f"(c[1]), "+f"(c[2]), "+f"(c[3])
        : "r"(a[0]), "r"(a[1]), "r"(a[2]), "r"(a[3]), "r"(b[0]), "r"(b[1]));
}

__device__ __forceinline__ void mma_f16(float* c, const uint32_t* a,
                                        const uint32_t* b) {
    asm volatile(
        "mma.sync.aligned.m16n8k16.row.col.f32.f16.f16.f32 "
        "{%0,%1,%2,%3}, {%4,%5,%6,%7}, {%8,%9}, {%0,%1,%2,%3};"
        : "+f"(c[0]), "+f"(c[1]), "+f"(c[2]), "+f"(c[3])
        : "r"(a[0]), "r"(a[1]), "r"(a[2]), "r"(a[3]), "r"(b[0]), "r"(b[1]));
}

__device__ __forceinline__ void ldsm4(uint32_t* r, uint32_t a) {
    asm volatile("ldmatrix.sync.aligned.m8n8.x4.shared.b16 {%0,%1,%2,%3}, [%4];"
        : "=r"(r[0]), "=r"(r[1]), "=r"(r[2]), "=r"(r[3]) : "r"(a));
}
__device__ __forceinline__ void ldsm2(uint32_t* r, uint32_t a) {
    asm volatile("ldmatrix.sync.aligned.m8n8.x2.shared.b16 {%0,%1}, [%2];"
        : "=r"(r[0]), "=r"(r[1]) : "r"(a));
}
__device__ __forceinline__ void ldsm2t(uint32_t* r, uint32_t a) {
    asm volatile("ldmatrix.sync.aligned.m8n8.x2.trans.shared.b16 {%0,%1}, [%2];"
        : "=r"(r[0]), "=r"(r[1]) : "r"(a));
}

// ---------------------------------------------------------------------------
// tf32 mma.sync GEMM: C[M,N] = A[M,K] @ Bt[N,K]^T   (fp32 in/out)  [UNCHANGED]
// ---------------------------------------------------------------------------
#define GEMM_SMEM (2 * 9216 * 4)

__global__ __launch_bounds__(256)
void sgemm_mma(const float* __restrict__ A, const float* __restrict__ Bt,
               float* __restrict__ C, int N, int K) {
    extern __shared__ float sm[];
    const int tid = threadIdx.x;
    const int lane = tid & 31, w = tid >> 5;
    const int wm = (w & 1) * 64;
    const int wn = (w >> 1) * 32;
    const int m0 = blockIdx.y * 128, n0 = blockIdx.x * 128;
    const uint32_t smb = smem_u32(sm);
    const int NC = K >> 5;

#define LOAD_CHUNK(c) do {                                                    \
    const int _ko = (c) * 32;                                                 \
    const uint32_t _bb = smb + ((c) & 1) * 36864u;                            \
    _Pragma("unroll")                                                         \
    for (int _j = 0; _j < 8; ++_j) {                                          \
        int _idx = tid + _j * 256;                                            \
        int _row = _idx >> 3, _seg = _idx & 7;                                \
        int _r = _row & 127;                                                  \
        const float* _g = (_row >= 128)                                       \
            ? (Bt + ((size_t)(n0 + _r) * K + _ko + _seg * 4))                 \
            : (A  + ((size_t)(m0 + _r) * K + _ko + _seg * 4));                \
        uint32_t _d = _bb + ((_row >= 128) ? 18432u : 0u)                     \
                      + (uint32_t)(_r * 144 + _seg * 16);                     \
        CP_ASYNC16(_d, _g);                                                   \
    }                                                                         \
    CP_COMMIT();                                                              \
} while (0)

    float acc[4][4][4];
#pragma unroll
    for (int i = 0; i < 4; ++i)
#pragma unroll
        for (int j = 0; j < 4; ++j)
#pragma unroll
            for (int k = 0; k < 4; ++k) acc[i][j][k] = 0.f;

    LOAD_CHUNK(0);

    for (int c = 0; c < NC; ++c) {
        if (c + 1 < NC) { LOAD_CHUNK(c + 1); CP_WAIT1(); }
        else CP_WAIT0();
        __syncthreads();

        const float* As = sm + (c & 1) * 9216;
        const float* Bs = As + 4608;
        const int rA = wm + (lane >> 2);
        const int rB = wn + (lane >> 2);
#pragma unroll
        for (int k8 = 0; k8 < 4; ++k8) {
            const int kc = k8 * 8 + (lane & 3);
            uint32_t af[4][4], bf[4][2];
#pragma unroll
            for (int t = 0; t < 4; ++t) {
                af[t][0] = tf32r(As[(rA + t * 16)     * 36 + kc]);
                af[t][1] = tf32r(As[(rA + t * 16 + 8) * 36 + kc]);
                af[t][2] = tf32r(As[(rA + t * 16)     * 36 + kc + 4]);
                af[t][3] = tf32r(As[(rA + t * 16 + 8) * 36 + kc + 4]);
            }
#pragma unroll
            for (int t = 0; t < 4; ++t) {
                bf[t][0] = tf32r(Bs[(rB + t * 8) * 36 + kc]);
                bf[t][1] = tf32r(Bs[(rB + t * 8) * 36 + kc + 4]);
            }
#pragma unroll
            for (int mt = 0; mt < 4; ++mt)
#pragma unroll
                for (int nt = 0; nt < 4; ++nt)
                    mma_tf32(acc[mt][nt], af[mt], bf[nt]);
        }
        __syncthreads();
    }

#pragma unroll
    for (int mt = 0; mt < 4; ++mt)
#pragma unroll
        for (int nt = 0; nt < 4; ++nt) {
            const int row = m0 + wm + mt * 16 + (lane >> 2);
            const int col = n0 + wn + nt * 8 + (lane & 3) * 2;
            *(float2*)&C[(size_t)row * N + col] =
                make_float2(acc[mt][nt][0], acc[mt][nt][1]);
            *(float2*)&C[(size_t)(row + 8) * N + col] =
                make_float2(acc[mt][nt][2], acc[mt][nt][3]);
        }
#undef LOAD_CHUNK
}

// ---------------------------------------------------------------------------
// Transpose [R,C] -> [C,R]. grid (C/32, R/32), block (32,8)
// ---------------------------------------------------------------------------
__global__ void transpose_kernel(const float* __restrict__ in,
                                 float* __restrict__ out, int R, int C) {
    __shared__ float t[32][33];
    const int c0 = blockIdx.x * 32, r0 = blockIdx.y * 32;
#pragma unroll
    for (int i = threadIdx.y; i < 32; i += 8)
        t[i][threadIdx.x] = in[(size_t)(r0 + i) * C + c0 + threadIdx.x];
    __syncthreads();
#pragma unroll
    for (int i = threadIdx.y; i < 32; i += 8)
        out[(size_t)(c0 + i) * R + r0 + threadIdx.x] = t[threadIdx.x][i];
}

// ---------------------------------------------------------------------------
// RMSNorm + RoPE; emits fp16 Q(hi/lo, pre-scaled), K, V in head-major layouts.
// grid.x = B*S, grid.y = 24 (0-15 Q, 16-19 K, 20-23 V), 128 threads.
// ---------------------------------------------------------------------------
__global__ void normrope_kernel(const int* __restrict__ positions,
                                const float* __restrict__ qscale,
                                const float* __restrict__ kscale) {
    const int bs = blockIdx.x, slot = blockIdx.y, t = threadIdx.x;
    const int b = bs >> 11, s = bs & (S_ - 1);

    if (slot >= 20) {  // V: convert to fp16
        int kvh = slot - 20;
        float v = g_v_raw[(size_t)bs * 512 + kvh * 128 + t];
        g_vh[((size_t)(b * KV_ + kvh) * S_ + s) * D_ + t] = __float2half_rn(v);
        return;
    }

    const float* in;
    const float* scale;
    if (slot < 16) {
        in = g_q_raw + (size_t)bs * 2048 + slot * 128;
        scale = qscale;
    } else {
        in = g_k_raw + (size_t)bs * 512 + (slot - 16) * 128;
        scale = kscale;
    }

    float x = in[t];
    float ss = x * x;
#pragma unroll
    for (int o = 16; o; o >>= 1) ss += __shfl_xor_sync(~0u, ss, o);
    __shared__ float wsum[4];
    __shared__ float sv[128];
    if ((t & 31) == 0) wsum[t >> 5] = ss;
    __syncthreads();
    ss = wsum[0] + wsum[1] + wsum[2] + wsum[3];
    float y = x * rsqrtf(ss * (1.0f / 128.0f) + 1e-6f) * scale[t];
    sv[t] = y;
    __syncthreads();

    const int pos = positions[bs];
    const int i = t & 63;
    double ang = (double)pos * exp(-(double)i * (9.210340371976184 / 64.0));
    double sn, cs;
    sincos(ang, &sn, &cs);
    float cf = (float)cs, sf = (float)sn;
    float o;
    if (t < 64) o = y * cf - sv[t + 64] * sf;
    else        o = y * cf + sv[t - 64] * sf;

    if (slot < 16) {
        float qs = o * SCALEF;
        __half hh = __float2half_rn(qs);
        __half hl = __float2half_rn(qs - __half2float(hh));
        size_t idx = ((size_t)(b * H_ + slot) * S_ + s) * D_ + t;
        g_qh[idx] = hh;
        g_ql[idx] = hl;
    } else {
        size_t idx = ((size_t)(b * KV_ + (slot - 16)) * S_ + s) * D_ + t;
        g_kh[idx] = __float2half_rn(o);
    }
}

// ---------------------------------------------------------------------------
// Tensor-core windowed flash attention with softcap.
// fp16 mma.sync m16n8k16. Q split hi/lo (2-product QK), P split hi/lo
// (2-product PV), K/V single fp16 -> ~3e-4 added error.
// grid (S/128, B*H), 256 threads (8 warps, 16 q-rows each).
// smem halves: QH 0, QL 17408, K0 34816, K1 43520, V0 52224, V1 60928,
//              PH 69632, PL 78848  (total 88064 halves = 176128 B)
// ---------------------------------------------------------------------------
#define AT_SMEM 176128
#define OQH 0
#define OQL 17408
#define OK0 34816
#define OK1 43520
#define OV0 52224
#define OV1 60928
#define OPH 69632
#define OPL 78848

__global__ __launch_bounds__(256, 1)
void attn_mma(const __half* __restrict__ Qh, const __half* __restrict__ Ql,
              const __half* __restrict__ Kh, const __half* __restrict__ Vh,
              float* __restrict__ ctx) {
    extern __shared__ __align__(16) __half smh[];
    const int tid = threadIdx.x, lane = tid & 31, w = tid >> 5;
    const int q0 = blockIdx.x * 128;
    const int bh = blockIdx.y, b = bh >> 4, h = bh & 15, kvh = (h & 15) >> 2;
    const __half* qhp = Qh + ((size_t)bh * S_ + q0) * D_;
    const __half* qlp = Ql + ((size_t)bh * S_ + q0) * D_;
    const __half* kp = Kh + (size_t)(b * KV_ + kvh) * S_ * D_;
    const __half* vp = Vh + (size_t)(b * KV_ + kvh) * S_ * D_;
    const uint32_t smb = smem_u32(smh);

    // Q hi+lo: 4096 x 16B, 16 per thread
#pragma unroll
    for (int j = 0; j < 16; ++j) {
        int idx = tid + j * 256;
        int which = idx >> 11;              // 0 hi, 1 lo
        int r = (idx >> 4) & 127;
        int seg = idx & 15;
        const __half* src = (which ? qlp : qhp) + r * 128 + seg * 8;
        uint32_t dst = smb + (uint32_t)(((which ? OQL : OQH) + r * 136 + seg * 8) * 2);
        CP_ASYNC16(dst, src);
    }

    int jt0 = q0 - (WIN_ - 1);
    if (jt0 < 0) jt0 = 0;
    jt0 &= ~63;
    const int ntl = (q0 + 128 - jt0) >> 6;

#define LOAD_KV(jt, kb, vb) do {                                              \
    _Pragma("unroll")                                                         \
    for (int _j = 0; _j < 8; ++_j) {                                          \
        int _idx = tid + _j * 256;                                            \
        int _wh = _idx >> 10;                                                 \
        int _r = (_idx >> 4) & 63;                                            \
        int _seg = _idx & 15;                                                 \
        const __half* _src = (_wh ? vp : kp) + (size_t)((jt) + _r) * 128 + _seg * 8; \
        uint32_t _dst = smb + (uint32_t)((((_wh) ? (vb) : (kb)) + _r * 136 + _seg * 8) * 2); \
        CP_ASYNC16(_dst, _src);                                               \
    }                                                                         \
} while (0)

    LOAD_KV(jt0, OK0, OV0);
    CP_COMMIT();   // group: Q + tile0

    float acc[16][4];
#pragma unroll
    for (int i = 0; i < 16; ++i)
#pragma unroll
        for (int j = 0; j < 4; ++j) acc[i][j] = 0.f;
    float mrow0 = -1e30f, mrow1 = -1e30f, lrow0 = 0.f, lrow1 = 0.f;

    const int m0w = w * 16;
    // ldmatrix lane address components
    const int a_row = m0w + (lane & 7) + ((lane >> 3) & 1) * 8;
    const int a_col = ((lane >> 4) & 1) * 8;
    const uint32_t aqh = smb + (uint32_t)((OQH + a_row * 136 + a_col) * 2);
    const uint32_t aql = smb + (uint32_t)((OQL + a_row * 136 + a_col) * 2);
    const uint32_t aph = smb + (uint32_t)((OPH + a_row * 72 + a_col) * 2);
    const uint32_t apl = smb + (uint32_t)((OPL + a_row * 72 + a_col) * 2);
    const int b_row = (lane & 7) + ((lane >> 3) & 1) * 8;   // for V (trans)
    const int bk_off = ((lane & 7) * 136 + ((lane >> 3) & 1) * 8) * 2;  // for K

    for (int it = 0; it < ntl; ++it) {
        const int jt = jt0 + it * 64;
        __syncthreads();   // everyone done with the buffer we are about to fill
        if (it + 1 < ntl) LOAD_KV(jt + 64, ((it + 1) & 1) ? OK1 : OK0,
                                  ((it + 1) & 1) ? OV1 : OV0);
        CP_COMMIT();
        CP_WAIT1();        // tile `it` (and Q) resident
        __syncthreads();

        const uint32_t kbase = smb + (uint32_t)(((it & 1) ? OK1 : OK0) * 2);
        const uint32_t vbase = smb + (uint32_t)(((it & 1) ? OV1 : OV0) * 2);

        // ---- S = (Qh + Ql) K^T ----
        float sf[8][4];
#pragma unroll
        for (int i = 0; i < 8; ++i)
#pragma unroll
            for (int j = 0; j < 4; ++j) sf[i][j] = 0.f;

#pragma unroll
        for (int k16 = 0; k16 < 8; ++k16) {
            uint32_t ah[4], al[4];
            ldsm4(ah, aqh + k16 * 32);
            ldsm4(al, aql + k16 * 32);
#pragma unroll
            for (int nt = 0; nt < 8; ++nt) {
                uint32_t bb[2];
                ldsm2(bb, kbase + (uint32_t)(bk_off + (nt * 8 * 136 + k16 * 16) * 2));
                mma_f16(sf[nt], ah, bb);
                mma_f16(sf[nt], al, bb);
            }
        }

        // ---- softcap + mask + online softmax ----
        const int r0 = q0 + m0w + (lane >> 2);
        const int r1 = r0 + 8;
        const int cb = jt + (lane & 3) * 2;
        float mx0 = -1e30f, mx1 = -1e30f;
#pragma unroll
        for (int nt = 0; nt < 8; ++nt) {
#pragma unroll
            for (int e = 0; e < 2; ++e) {
                const int col = cb + nt * 8 + e;
                {
                    float v = sf[nt][e];
                    float z = __expf(v * 0.04f);
                    float tt = 50.f * __fdividef(z - 1.f, z + 1.f);
                    bool ok = (col <= r0) && (r0 - col < WIN_);
                    v = ok ? tt : -1e30f;
                    sf[nt][e] = v;
                    mx0 = fmaxf(mx0, v);
                }
                {
                    float v = sf[nt][2 + e];
                    float z = __expf(v * 0.04f);
                    float tt = 50.f * __fdividef(z - 1.f, z + 1.f);
                    bool ok = (col <= r1) && (r1 - col < WIN_);
                    v = ok ? tt : -1e30f;
                    sf[nt][2 + e] = v;
                    mx1 = fmaxf(mx1, v);
                }
            }
        }
        mx0 = fmaxf(mx0, __shfl_xor_sync(~0u, mx0, 1));
        mx0 = fmaxf(mx0, __shfl_xor_sync(~0u, mx0, 2));
        mx1 = fmaxf(mx1, __shfl_xor_sync(~0u, mx1, 1));
        mx1 = fmaxf(mx1, __shfl_xor_sync(~0u, mx1, 2));
        const float mn0 = fmaxf(mrow0, mx0), mn1 = fmaxf(mrow1, mx1);
        const float al0 = __expf(mrow0 - mn0), al1 = __expf(mrow1 - mn1);
        mrow0 = mn0; mrow1 = mn1;

        __syncwarp();
        float s0 = 0.f, s1 = 0.f;
        const int prow0 = m0w + (lane >> 2);
        const int pc = (lane & 3) * 2;
#pragma unroll
        for (int nt = 0; nt < 8; ++nt) {
            float p0 = (sf[nt][0] > -1e29f) ? __expf(sf[nt][0] - mn0) : 0.f;
            float p1 = (sf[nt][1] > -1e29f) ? __expf(sf[nt][1] - mn0) : 0.f;
            float p2 = (sf[nt][2] > -1e29f) ? __expf(sf[nt][2] - mn1) : 0.f;
            float p3 = (sf[nt][3] > -1e29f) ? __expf(sf[nt][3] - mn1) : 0.f;
            s0 += p0 + p1;
            s1 += p2 + p3;
            __half h0 = __float2half_rn(p0), h1 = __float2half_rn(p1);
            __half h2 = __float2half_rn(p2), h3 = __float2half_rn(p3);
            __half l0 = __float2half_rn(p0 - __half2float(h0));
            __half l1 = __float2half_rn(p1 - __half2float(h1));
            __half l2 = __float2half_rn(p2 - __half2float(h2));
            __half l3 = __float2half_rn(p3 - __half2float(h3));
            const int c = nt * 8 + pc;
            *(__half2*)(smh + OPH + prow0 * 72 + c)       = __halves2half2(h0, h1);
            *(__half2*)(smh + OPH + (prow0 + 8) * 72 + c) = __halves2half2(h2, h3);
            *(__half2*)(smh + OPL + prow0 * 72 + c)       = __halves2half2(l0, l1);
            *(__half2*)(smh + OPL + (prow0 + 8) * 72 + c) = __halves2half2(l2, l3);
        }
        s0 += __shfl_xor_sync(~0u, s0, 1);
        s0 += __shfl_xor_sync(~0u, s0, 2);
        s1 += __shfl_xor_sync(~0u, s1, 1);
        s1 += __shfl_xor_sync(~0u, s1, 2);
        lrow0 = lrow0 * al0 + s0;
        lrow1 = lrow1 * al1 + s1;
#pragma unroll
        for (int nt = 0; nt < 16; ++nt) {
            acc[nt][0] *= al0; acc[nt][1] *= al0;
            acc[nt][2] *= al1; acc[nt][3] *= al1;
        }
        __syncwarp();

        // ---- O += (Ph + Pl) V ----
#pragma unroll
        for (int k16 = 0; k16 < 4; ++k16) {
            uint32_t ph4[4], pl4[4];
            ldsm4(ph4, aph + k16 * 32);
            ldsm4(pl4, apl + k16 * 32);
#pragma unroll
            for (int nt = 0; nt < 16; ++nt) {
                uint32_t bb[2];
                ldsm2t(bb, vbase +
                       (uint32_t)(((k16 * 16 + b_row) * 136 + nt * 8) * 2));
                mma_f16(acc[nt], ph4, bb);
                mma_f16(acc[nt], pl4, bb);
            }
        }
    }

    // epilogue: normalize, write ctx[b, s, h, d] fp32
    const float i0 = 1.f / lrow0, i1 = 1.f / lrow1;
    const int row0 = q0 + m0w + (lane >> 2);
    float* c0 = ctx + ((size_t)(b * S_ + row0) * H_ + h) * D_ + (lane & 3) * 2;
    float* c1 = c0 + (size_t)8 * H_ * D_;
#pragma unroll
    for (int nt = 0; nt < 16; ++nt) {
        *(float2*)(c0 + nt * 8) = make_float2(acc[nt][0] * i0, acc[nt][1] * i0);
        *(float2*)(c1 + nt * 8) = make_float2(acc[nt][2] * i1, acc[nt][3] * i1);
    }
#undef LOAD_KV
}

// ---------------------------------------------------------------------------
// kernel_launch
// inputs: 0:x 1:positions 2:mask(unused) 3:Wq 4:Wk 5:Wv 6:Wo 7:q_norm 8:k_norm
// ---------------------------------------------------------------------------
extern "C" void kernel_launch(void* const* d_in, const int* in_sizes, int n_in,
                              void* d_out, int out_size) {
    (void)in_sizes; (void)n_in; (void)out_size;
    const float* x   = (const float*)d_in[0];
    const int* pos   = (const int*)d_in[1];
    const float* Wq  = (const float*)d_in[3];
    const float* Wk  = (const float*)d_in[4];
    const float* Wv  = (const float*)d_in[5];
    const float* Wo  = (const float*)d_in[6];
    const float* qns = (const float*)d_in[7];
    const float* kns = (const float*)d_in[8];
    float* out = (float*)d_out;

    float *wqt, *wkt, *wvt, *wot, *qraw, *kraw, *vraw, *ctx;
    __half *qh, *ql, *kh, *vh;
    cudaGetSymbolAddress((void**)&wqt, g_wqt);
    cudaGetSymbolAddress((void**)&wkt, g_wkt);
    cudaGetSymbolAddress((void**)&wvt, g_wvt);
    cudaGetSymbolAddress((void**)&wot, g_wot);
    cudaGetSymbolAddress((void**)&qraw, g_q_raw);
    cudaGetSymbolAddress((void**)&kraw, g_k_raw);
    cudaGetSymbolAddress((void**)&vraw, g_v_raw);
    cudaGetSymbolAddress((void**)&qh, g_qh);
    cudaGetSymbolAddress((void**)&ql, g_ql);
    cudaGetSymbolAddress((void**)&kh, g_kh);
    cudaGetSymbolAddress((void**)&vh, g_vh);
    cudaGetSymbolAddress((void**)&ctx, g_ctx);

    cudaFuncSetAttribute(sgemm_mma,
                         cudaFuncAttributeMaxDynamicSharedMemorySize, GEMM_SMEM);
    cudaFuncSetAttribute(attn_mma,
                         cudaFuncAttributeMaxDynamicSharedMemorySize, AT_SMEM);

    // 1. transpose weights to [N,K]
    {
        dim3 blk(32, 8);
        transpose_kernel<<<dim3(2048 / 32, 2048 / 32), blk>>>(Wq, wqt, 2048, 2048);
        transpose_kernel<<<dim3(512 / 32, 2048 / 32), blk>>>(Wk, wkt, 2048, 512);
        transpose_kernel<<<dim3(512 / 32, 2048 / 32), blk>>>(Wv, wvt, 2048, 512);
        transpose_kernel<<<dim3(2048 / 32, 2048 / 32), blk>>>(Wo, wot, 2048, 2048);
    }
    // 2. QKV projections (tf32 mma.sync)
    {
        sgemm_mma<<<dim3(2048 / 128, BS_ / 128), 256, GEMM_SMEM>>>(x, wqt, qraw, 2048, 2048);
        sgemm_mma<<<dim3(512 / 128, BS_ / 128), 256, GEMM_SMEM>>>(x, wkt, kraw, 512, 2048);
        sgemm_mma<<<dim3(512 / 128, BS_ / 128), 256, GEMM_SMEM>>>(x, wvt, vraw, 512, 2048);
    }
    // 3. RMSNorm + RoPE + fp16 conversion/split
    {
        dim3 g(BS_, 24);
        normrope_kernel<<<g, 128>>>(pos, qns, kns);
    }
    // 4. Attention (fp16 mma.sync, error-compensated)
    {
        dim3 g(S_ / 128, B_ * H_);
        attn_mma<<<g, 256, AT_SMEM>>>(qh, ql, kh, vh, ctx);
    }
    // 5. Output projection
    {
        sgemm_mma<<<dim3(2048 / 128, BS_ / 128), 256, GEMM_SMEM>>>(ctx, wot, out, 2048, 2048);
    }
}

// round 5
// speedup vs baseline: 5.7356x; 1.7370x over previous
#include <cuda_runtime.h>
#include <cuda_fp16.h>
#include <math.h>
#include <stdint.h>

// ---------------------------------------------------------------------------
// Problem constants
// ---------------------------------------------------------------------------
#define B_   2
#define S_   2048
#define E_   2048
#define H_   16
#define KV_  4
#define D_   128
#define WIN_ 1024
#define SCALEF 0.08838834764831845f   // 1/sqrt(128)
#define BS_  (B_*S_)                   // 4096

// ---------------------------------------------------------------------------
// Scratch (static device globals)
// ---------------------------------------------------------------------------
__device__ __half g_xh[(size_t)BS_*2048];     // x fp16
__device__ __half g_wqh[(size_t)2048*2048];   // Wq fp16 [K][N]
__device__ __half g_wkh[(size_t)2048*512];
__device__ __half g_wvh[(size_t)2048*512];
__device__ __half g_woh[(size_t)2048*2048];   // Wo fp16 [HD][E]
__device__ float g_q_raw[(size_t)BS_*2048];   // [B*S, H*D] fp32
__device__ float g_k_raw[(size_t)BS_*512];
__device__ float g_v_raw[(size_t)BS_*512];
__device__ float2 g_tbl[(size_t)BS_*64];      // rope cos/sin table
__device__ __half g_qh[(size_t)BS_*2048];     // [B,H,S,D] fp16 hi (scaled)
__device__ __half g_ql[(size_t)BS_*2048];     // fp16 lo residual
__device__ __half g_kh[(size_t)BS_*512];      // [B,KV,S,D]
__device__ __half g_vh[(size_t)BS_*512];
__device__ __half g_ctxh[(size_t)BS_*2048];   // [B*S, H*D] fp16

// ---------------------------------------------------------------------------
// Helpers
// ---------------------------------------------------------------------------
__device__ __forceinline__ uint32_t smem_u32(const void* p) {
    uint32_t a;
    asm("{ .reg .u64 t; cvta.to.shared.u64 t, %1; cvt.u32.u64 %0, t; }"
        : "=r"(a) : "l"(p));
    return a;
}

#define CP_ASYNC16(dst_u32, gptr) \
    asm volatile("cp.async.cg.shared.global [%0], [%1], 16;" \
                 :: "r"(dst_u32), "l"(gptr) : "memory")
#define CP_COMMIT() asm volatile("cp.async.commit_group;" ::: "memory")
#define CP_WAIT1()  asm volatile("cp.async.wait_group 1;" ::: "memory")
#define CP_WAIT0()  asm volatile("cp.async.wait_group 0;" ::: "memory")

__device__ __forceinline__ void mma_f16(float* c, const uint32_t* a,
                                        const uint32_t* b) {
    asm volatile(
        "mma.sync.aligned.m16n8k16.row.col.f32.f16.f16.f32 "
        "{%0,%1,%2,%3}, {%4,%5,%6,%7}, {%8,%9}, {%0,%1,%2,%3};"
        : "+f"(c[0]), "+f"(c[1]), "+f"(c[2]), "+f"(c[3])
        : "r"(a[0]), "r"(a[1]), "r"(a[2]), "r"(a[3]), "r"(b[0]), "r"(b[1]));
}

__device__ __forceinline__ void ldsm4(uint32_t* r, uint32_t a) {
    asm volatile("ldmatrix.sync.aligned.m8n8.x4.shared.b16 {%0,%1,%2,%3}, [%4];"
        : "=r"(r[0]), "=r"(r[1]), "=r"(r[2]), "=r"(r[3]) : "r"(a));
}
__device__ __forceinline__ void ldsm4t(uint32_t* r, uint32_t a) {
    asm volatile("ldmatrix.sync.aligned.m8n8.x4.trans.shared.b16 {%0,%1,%2,%3}, [%4];"
        : "=r"(r[0]), "=r"(r[1]), "=r"(r[2]), "=r"(r[3]) : "r"(a));
}

// ---------------------------------------------------------------------------
// fp32 -> fp16 convert (vectorized)
// ---------------------------------------------------------------------------
__global__ void cvt_h(const float* __restrict__ in, __half* __restrict__ out,
                      int n4) {
    int i = blockIdx.x * blockDim.x + threadIdx.x;
    if (i < n4) {
        float4 v = ((const float4*)in)[i];
        __half2 a = __floats2half2_rn(v.x, v.y);
        __half2 b = __floats2half2_rn(v.z, v.w);
        ((__half2*)out)[i * 2] = a;
        ((__half2*)out)[i * 2 + 1] = b;
    }
}

// ---------------------------------------------------------------------------
// RoPE cos/sin table (double precision, tiny kernel)
// ---------------------------------------------------------------------------
__global__ void rope_table_kernel(const int* __restrict__ positions) {
    int idx = blockIdx.x * 256 + threadIdx.x;   // BS_*64 total
    int bs = idx >> 6, i = idx & 63;
    double ang = (double)positions[bs] * exp(-(double)i * (9.210340371976184 / 64.0));
    double sn, cs;
    sincos(ang, &sn, &cs);
    g_tbl[idx] = make_float2((float)cs, (float)sn);
}

// ---------------------------------------------------------------------------
// fp16 mma GEMM: C[M,N] = A[M,K] @ B[K,N]   (A,B fp16 row-major, C fp32)
// 128x128 CTA tile, K chunk 64, double-buffered cp.async, ldmatrix.
// 8 warps 2(m) x 4(n): warp tile 64x32. grid (N/128, M/128), 256 thr.
// smem: 2 x (A[128][72] + B[64][136]) halves = 71680 B
// ---------------------------------------------------------------------------
#define GEMM_SMEM 71680
#define GA_STRIDE 72
#define GB_STRIDE 136
#define GBUF (9216 + 8704)   // halves per buffer

__global__ __launch_bounds__(256)
void sgemm_h(const __half* __restrict__ A, const __half* __restrict__ B,
             float* __restrict__ C, int N, int K) {
    extern __shared__ __align__(16) __half smg[];
    const int tid = threadIdx.x;
    const int lane = tid & 31, w = tid >> 5;
    const int wm = (w & 1) * 64, wn = (w >> 1) * 32;
    const int m0 = blockIdx.y * 128, n0 = blockIdx.x * 128;
    const uint32_t smb = smem_u32(smg);
    const int NC = K >> 6;

#define G_LOAD(c) do {                                                        \
    const int _ko = (c) << 6;                                                 \
    const uint32_t _bb = smb + (uint32_t)(((c) & 1) * GBUF * 2);              \
    _Pragma("unroll")                                                         \
    for (int _j = 0; _j < 8; ++_j) {                                          \
        int _idx = tid + _j * 256;                                            \
        if (_idx < 1024) {   /* A: 128 rows x 8 segs */                       \
            int _r = _idx >> 3, _seg = _idx & 7;                              \
            CP_ASYNC16(_bb + (uint32_t)((_r * GA_STRIDE + _seg * 8) * 2),     \
                       A + (size_t)(m0 + _r) * K + _ko + _seg * 8);           \
        } else {             /* B: 64 rows x 16 segs */                       \
            int _i = _idx - 1024;                                             \
            int _r = _i >> 4, _seg = _i & 15;                                 \
            CP_ASYNC16(_bb + (uint32_t)((9216 + _r * GB_STRIDE + _seg * 8) * 2), \
                       B + (size_t)(_ko + _r) * N + n0 + _seg * 8);           \
        }                                                                     \
    }                                                                         \
    CP_COMMIT();                                                              \
} while (0)

    float acc[4][4][4];
#pragma unroll
    for (int i = 0; i < 4; ++i)
#pragma unroll
        for (int j = 0; j < 4; ++j)
#pragma unroll
            for (int k = 0; k < 4; ++k) acc[i][j][k] = 0.f;

    G_LOAD(0);

    // ldmatrix address components
    const int a_row = (lane & 7) + ((lane >> 3) & 1) * 8;
    const int a_csel = ((lane >> 4) & 1) * 8;
    const int b_krow = ((lane >> 3) & 1) * 8 + (lane & 7);
    const int b_nsel = ((lane >> 4) & 1) * 8;

    for (int c = 0; c < NC; ++c) {
        if (c + 1 < NC) { G_LOAD(c + 1); CP_WAIT1(); }
        else CP_WAIT0();
        __syncthreads();

        const uint32_t ab = smb + (uint32_t)((c & 1) * GBUF * 2);
        const uint32_t bb = ab + 9216u * 2;
#pragma unroll
        for (int k16 = 0; k16 < 4; ++k16) {
            uint32_t af[4][4], bf[2][4];
#pragma unroll
            for (int mt = 0; mt < 4; ++mt)
                ldsm4(af[mt], ab + (uint32_t)(((wm + mt * 16 + a_row) * GA_STRIDE
                                               + k16 * 16 + a_csel) * 2));
#pragma unroll
            for (int np = 0; np < 2; ++np)
                ldsm4t(bf[np], bb + (uint32_t)(((k16 * 16 + b_krow) * GB_STRIDE
                                                + wn + np * 16 + b_nsel) * 2));
#pragma unroll
            for (int mt = 0; mt < 4; ++mt)
#pragma unroll
                for (int nt = 0; nt < 4; ++nt)
                    mma_f16(acc[mt][nt], af[mt], bf[nt >> 1] + (nt & 1) * 2);
        }
        __syncthreads();
    }

#pragma unroll
    for (int mt = 0; mt < 4; ++mt)
#pragma unroll
        for (int nt = 0; nt < 4; ++nt) {
            const int row = m0 + wm + mt * 16 + (lane >> 2);
            const int col = n0 + wn + nt * 8 + (lane & 3) * 2;
            *(float2*)&C[(size_t)row * N + col] =
                make_float2(acc[mt][nt][0], acc[mt][nt][1]);
            *(float2*)&C[(size_t)(row + 8) * N + col] =
                make_float2(acc[mt][nt][2], acc[mt][nt][3]);
        }
#undef G_LOAD
}

// ---------------------------------------------------------------------------
// RMSNorm + RoPE (table-based); emits fp16 Q hi/lo (scaled), K, V.
// grid.x = B*S, grid.y = 24, 128 threads.
// ---------------------------------------------------------------------------
__global__ void normrope_kernel(const float* __restrict__ qscale,
                                const float* __restrict__ kscale) {
    const int bs = blockIdx.x, slot = blockIdx.y, t = threadIdx.x;
    const int b = bs >> 11, s = bs & (S_ - 1);

    if (slot >= 20) {  // V
        int kvh = slot - 20;
        float v = g_v_raw[(size_t)bs * 512 + kvh * 128 + t];
        g_vh[((size_t)(b * KV_ + kvh) * S_ + s) * D_ + t] = __float2half_rn(v);
        return;
    }

    const float* in;
    const float* scale;
    if (slot < 16) {
        in = g_q_raw + (size_t)bs * 2048 + slot * 128;
        scale = qscale;
    } else {
        in = g_k_raw + (size_t)bs * 512 + (slot - 16) * 128;
        scale = kscale;
    }

    float x = in[t];
    float ss = x * x;
#pragma unroll
    for (int o = 16; o; o >>= 1) ss += __shfl_xor_sync(~0u, ss, o);
    __shared__ float wsum[4];
    __shared__ float sv[128];
    if ((t & 31) == 0) wsum[t >> 5] = ss;
    __syncthreads();
    ss = wsum[0] + wsum[1] + wsum[2] + wsum[3];
    float y = x * rsqrtf(ss * (1.0f / 128.0f) + 1e-6f) * scale[t];
    sv[t] = y;
    __syncthreads();

    float2 cssn = g_tbl[(size_t)bs * 64 + (t & 63)];
    float o;
    if (t < 64) o = y * cssn.x - sv[t + 64] * cssn.y;
    else        o = y * cssn.x + sv[t - 64] * cssn.y;

    if (slot < 16) {
        float qs = o * SCALEF;
        __half hh = __float2half_rn(qs);
        __half hl = __float2half_rn(qs - __half2float(hh));
        size_t idx = ((size_t)(b * H_ + slot) * S_ + s) * D_ + t;
        g_qh[idx] = hh;
        g_ql[idx] = hl;
    } else {
        size_t idx = ((size_t)(b * KV_ + (slot - 16)) * S_ + s) * D_ + t;
        g_kh[idx] = __float2half_rn(o);
    }
}

// ---------------------------------------------------------------------------
// Tensor-core windowed flash attention v2.
// BM=128, BN=128. Q hi/lo in smem (loaded once), K/V double-buffered,
// P kept entirely in registers (S-accum fragment == PV A-fragment layout).
// grid (S/128 reversed, B*H), 256 threads (8 warps x 16 q-rows).
// smem halves: QH 0, QL 17408, K0 34816, K1 52224, V0 69632, V1 87040
// total 104448 halves = 208896 B
// ---------------------------------------------------------------------------
#define AT_SMEM 208896
#define OQH 0
#define OQL 17408
#define OK0 34816
#define OK1 52224
#define OV0 69632
#define OV1 87040

__global__ __launch_bounds__(256, 1)
void attn_mma2(const __half* __restrict__ Qh, const __half* __restrict__ Ql,
               const __half* __restrict__ Kh, const __half* __restrict__ Vh,
               __half* __restrict__ ctx) {
    extern __shared__ __align__(16) __half smh[];
    const int tid = threadIdx.x, lane = tid & 31, w = tid >> 5;
    const int qt = gridDim.x - 1 - blockIdx.x;     // long blocks first
    const int q0 = qt * 128;
    const int bh = blockIdx.y, b = bh >> 4, h = bh & 15, kvh = (h & 15) >> 2;
    const __half* qhp = Qh + ((size_t)bh * S_ + q0) * D_;
    const __half* qlp = Ql + ((size_t)bh * S_ + q0) * D_;
    const __half* kp = Kh + (size_t)(b * KV_ + kvh) * S_ * D_;
    const __half* vp = Vh + (size_t)(b * KV_ + kvh) * S_ * D_;
    const uint32_t smb = smem_u32(smh);

    // Q hi+lo: 4096 x 16B chunks, 16 per thread
#pragma unroll
    for (int j = 0; j < 16; ++j) {
        int idx = tid + j * 256;
        int which = idx >> 11;
        int r = (idx >> 4) & 127;
        int seg = idx & 15;
        const __half* src = (which ? qlp : qhp) + r * 128 + seg * 8;
        uint32_t dst = smb + (uint32_t)(((which ? OQL : OQH) + r * 136 + seg * 8) * 2);
        CP_ASYNC16(dst, src);
    }

    int jt0 = q0 - (WIN_ - 1);
    if (jt0 < 0) jt0 = 0;
    jt0 &= ~127;
    const int ntl = (q0 + 128 - jt0) >> 7;

#define LOAD_KV(jt, kb, vb) do {                                              \
    _Pragma("unroll")                                                         \
    for (int _j = 0; _j < 16; ++_j) {                                         \
        int _idx = tid + _j * 256;                                            \
        int _wh = _idx >> 11;                                                 \
        int _r = (_idx >> 4) & 127;                                           \
        int _seg = _idx & 15;                                                 \
        const __half* _src = (_wh ? vp : kp) + (size_t)((jt) + _r) * 128 + _seg * 8; \
        uint32_t _dst = smb + (uint32_t)((((_wh) ? (vb) : (kb)) + _r * 136 + _seg * 8) * 2); \
        CP_ASYNC16(_dst, _src);                                               \
    }                                                                         \
} while (0)

    LOAD_KV(jt0, OK0, OV0);
    CP_COMMIT();

    float acc[16][4];
#pragma unroll
    for (int i = 0; i < 16; ++i)
#pragma unroll
        for (int j = 0; j < 4; ++j) acc[i][j] = 0.f;
    float mrow0 = -1e30f, mrow1 = -1e30f, lrow0 = 0.f, lrow1 = 0.f;

    const int m0w = w * 16;
    const int a_row = m0w + (lane & 7) + ((lane >> 3) & 1) * 8;
    const int a_col = ((lane >> 4) & 1) * 8;
    const uint32_t aqh = smb + (uint32_t)((OQH + a_row * 136 + a_col) * 2);
    const uint32_t aql = smb + (uint32_t)((OQL + a_row * 136 + a_col) * 2);
    // K frag (x4, two n8 tiles): key = p*16 + ((lane>>4)&1)*8 + (lane&7), dsel
    const int k_off = ((((lane >> 4) & 1) * 8 + (lane & 7)) * 136
                       + ((lane >> 3) & 1) * 8) * 2;
    // V frag (x4 trans, two d8 tiles)
    const int v_row = ((lane >> 3) & 1) * 8 + (lane & 7);
    const int v_csel = ((lane >> 4) & 1) * 8;

    for (int it = 0; it < ntl; ++it) {
        const int jt = jt0 + it * 128;
        __syncthreads();
        if (it + 1 < ntl) {
            LOAD_KV(jt + 128, ((it + 1) & 1) ? OK1 : OK0,
                    ((it + 1) & 1) ? OV1 : OV0);
            CP_COMMIT();
            CP_WAIT1();
        } else {
            CP_COMMIT();
            CP_WAIT0();
        }
        __syncthreads();

        const uint32_t kbase = smb + (uint32_t)(((it & 1) ? OK1 : OK0) * 2);
        const uint32_t vbase = smb + (uint32_t)(((it & 1) ? OV1 : OV0) * 2);

        // ---- S = (Qh + Ql) K^T : 16 n-tiles of 8 keys ----
        float sf[16][4];
#pragma unroll
        for (int i = 0; i < 16; ++i)
#pragma unroll
            for (int j = 0; j < 4; ++j) sf[i][j] = 0.f;

#pragma unroll
        for (int k16 = 0; k16 < 8; ++k16) {
            uint32_t ah[4], al[4];
            ldsm4(ah, aqh + k16 * 32);
            ldsm4(al, aql + k16 * 32);
#pragma unroll
            for (int p = 0; p < 8; ++p) {
                uint32_t bb[4];
                ldsm4(bb, kbase + (uint32_t)(k_off + (p * 16 * 136 + k16 * 16) * 2));
                mma_f16(sf[2 * p],     ah, bb);
                mma_f16(sf[2 * p],     al, bb);
                mma_f16(sf[2 * p + 1], ah, bb + 2);
                mma_f16(sf[2 * p + 1], al, bb + 2);
            }
        }

        // ---- softcap + mask + online softmax ----
        const int r0 = q0 + m0w + (lane >> 2);
        const int r1 = r0 + 8;
        const int cb = jt + (lane & 3) * 2;
        const bool need_mask = (jt + 127 > q0 + m0w) ||
                               (jt < q0 + m0w + 15 - (WIN_ - 1));
        float mx0 = -1e30f, mx1 = -1e30f;
#pragma unroll
        for (int nt = 0; nt < 16; ++nt) {
#pragma unroll
            for (int e = 0; e < 2; ++e) {
                const int col = cb + nt * 8 + e;
                {
                    float v = sf[nt][e];
                    float z = __expf(v * 0.04f);
                    float tt = 50.f - __fdividef(100.f, z + 1.f);
                    bool ok = !need_mask || ((col <= r0) && (r0 - col < WIN_));
                    v = ok ? tt : -1e30f;
                    sf[nt][e] = v;
                    mx0 = fmaxf(mx0, v);
                }
                {
                    float v = sf[nt][2 + e];
                    float z = __expf(v * 0.04f);
                    float tt = 50.f - __fdividef(100.f, z + 1.f);
                    bool ok = !need_mask || ((col <= r1) && (r1 - col < WIN_));
                    v = ok ? tt : -1e30f;
                    sf[nt][2 + e] = v;
                    mx1 = fmaxf(mx1, v);
                }
            }
        }
        mx0 = fmaxf(mx0, __shfl_xor_sync(~0u, mx0, 1));
        mx0 = fmaxf(mx0, __shfl_xor_sync(~0u, mx0, 2));
        mx1 = fmaxf(mx1, __shfl_xor_sync(~0u, mx1, 1));
        mx1 = fmaxf(mx1, __shfl_xor_sync(~0u, mx1, 2));
        const float mn0 = fmaxf(mrow0, mx0), mn1 = fmaxf(mrow1, mx1);
        const float al0 = __expf(mrow0 - mn0), al1 = __expf(mrow1 - mn1);
        mrow0 = mn0; mrow1 = mn1;

        float s0 = 0.f, s1 = 0.f;
#pragma unroll
        for (int nt = 0; nt < 16; ++nt) {
            float p0 = (sf[nt][0] > -1e29f) ? __expf(sf[nt][0] - mn0) : 0.f;
            float p1 = (sf[nt][1] > -1e29f) ? __expf(sf[nt][1] - mn0) : 0.f;
            float p2 = (sf[nt][2] > -1e29f) ? __expf(sf[nt][2] - mn1) : 0.f;
            float p3 = (sf[nt][3] > -1e29f) ? __expf(sf[nt][3] - mn1) : 0.f;
            s0 += p0 + p1; s1 += p2 + p3;
            sf[nt][0] = p0; sf[nt][1] = p1; sf[nt][2] = p2; sf[nt][3] = p3;
        }
        s0 += __shfl_xor_sync(~0u, s0, 1);
        s0 += __shfl_xor_sync(~0u, s0, 2);
        s1 += __shfl_xor_sync(~0u, s1, 1);
        s1 += __shfl_xor_sync(~0u, s1, 2);
        lrow0 = lrow0 * al0 + s0;
        lrow1 = lrow1 * al1 + s1;
#pragma unroll
        for (int nt = 0; nt < 16; ++nt) {
            acc[nt][0] *= al0; acc[nt][1] *= al0;
            acc[nt][2] *= al1; acc[nt][3] *= al1;
        }

        // ---- O += (Ph + Pl) V, P fragments built in registers ----
#pragma unroll
        for (int k16 = 0; k16 < 8; ++k16) {
            const float* pa = sf[2 * k16];
            const float* pb = sf[2 * k16 + 1];
            uint32_t PH[4], PL[4];
            {
                __half2 h0 = __floats2half2_rn(pa[0], pa[1]);
                __half2 h1 = __floats2half2_rn(pa[2], pa[3]);
                __half2 h2 = __floats2half2_rn(pb[0], pb[1]);
                __half2 h3 = __floats2half2_rn(pb[2], pb[3]);
                float2 f0 = __half22float2(h0), f1 = __half22float2(h1);
                float2 f2 = __half22float2(h2), f3 = __half22float2(h3);
                __half2 l0 = __floats2half2_rn(pa[0] - f0.x, pa[1] - f0.y);
                __half2 l1 = __floats2half2_rn(pa[2] - f1.x, pa[3] - f1.y);
                __half2 l2 = __floats2half2_rn(pb[0] - f2.x, pb[1] - f2.y);
                __half2 l3 = __floats2half2_rn(pb[2] - f3.x, pb[3] - f3.y);
                PH[0] = *(uint32_t*)&h0; PH[1] = *(uint32_t*)&h1;
                PH[2] = *(uint32_t*)&h2; PH[3] = *(uint32_t*)&h3;
                PL[0] = *(uint32_t*)&l0; PL[1] = *(uint32_t*)&l1;
                PL[2] = *(uint32_t*)&l2; PL[3] = *(uint32_t*)&l3;
            }
#pragma unroll
            for (int p = 0; p < 8; ++p) {
                uint32_t bb[4];
                ldsm4t(bb, vbase + (uint32_t)(((k16 * 16 + v_row) * 136
                                               + p * 16 + v_csel) * 2));
                mma_f16(acc[2 * p],     PH, bb);
                mma_f16(acc[2 * p],     PL, bb);
                mma_f16(acc[2 * p + 1], PH, bb + 2);
                mma_f16(acc[2 * p + 1], PL, bb + 2);
            }
        }
    }

    // epilogue: normalize, write ctx fp16 [b, s, h, d]
    const float i0 = 1.f / lrow0, i1 = 1.f / lrow1;
    const int row0 = q0 + m0w + (lane >> 2);
    __half* c0 = ctx + ((size_t)(b * S_ + row0) * H_ + h) * D_ + (lane & 3) * 2;
    __half* c1 = c0 + (size_t)8 * H_ * D_;
#pragma unroll
    for (int nt = 0; nt < 16; ++nt) {
        *(__half2*)(c0 + nt * 8) = __floats2half2_rn(acc[nt][0] * i0, acc[nt][1] * i0);
        *(__half2*)(c1 + nt * 8) = __floats2half2_rn(acc[nt][2] * i1, acc[nt][3] * i1);
    }
#undef LOAD_KV
}

// ---------------------------------------------------------------------------
// kernel_launch
// inputs: 0:x 1:positions 2:mask(unused) 3:Wq 4:Wk 5:Wv 6:Wo 7:q_norm 8:k_norm
// ---------------------------------------------------------------------------
extern "C" void kernel_launch(void* const* d_in, const int* in_sizes, int n_in,
                              void* d_out, int out_size) {
    (void)in_sizes; (void)n_in; (void)out_size;
    const float* x   = (const float*)d_in[0];
    const int* pos   = (const int*)d_in[1];
    const float* Wq  = (const float*)d_in[3];
    const float* Wk  = (const float*)d_in[4];
    const float* Wv  = (const float*)d_in[5];
    const float* Wo  = (const float*)d_in[6];
    const float* qns = (const float*)d_in[7];
    const float* kns = (const float*)d_in[8];
    float* out = (float*)d_out;

    __half *xh, *wqh, *wkh, *wvh, *woh, *qh, *ql, *kh, *vh, *ctxh;
    float *qraw, *kraw, *vraw;
    cudaGetSymbolAddress((void**)&xh,  g_xh);
    cudaGetSymbolAddress((void**)&wqh, g_wqh);
    cudaGetSymbolAddress((void**)&wkh, g_wkh);
    cudaGetSymbolAddress((void**)&wvh, g_wvh);
    cudaGetSymbolAddress((void**)&woh, g_woh);
    cudaGetSymbolAddress((void**)&qraw, g_q_raw);
    cudaGetSymbolAddress((void**)&kraw, g_k_raw);
    cudaGetSymbolAddress((void**)&vraw, g_v_raw);
    cudaGetSymbolAddress((void**)&qh, g_qh);
    cudaGetSymbolAddress((void**)&ql, g_ql);
    cudaGetSymbolAddress((void**)&kh, g_kh);
    cudaGetSymbolAddress((void**)&vh, g_vh);
    cudaGetSymbolAddress((void**)&ctxh, g_ctxh);

    cudaFuncSetAttribute(sgemm_h,
                         cudaFuncAttributeMaxDynamicSharedMemorySize, GEMM_SMEM);
    cudaFuncSetAttribute(attn_mma2,
                         cudaFuncAttributeMaxDynamicSharedMemorySize, AT_SMEM);

    // 1. fp16 converts + rope table
    cvt_h<<<BS_ * 2048 / 4 / 256, 256>>>(x, xh, BS_ * 2048 / 4);
    cvt_h<<<2048 * 2048 / 4 / 256, 256>>>(Wq, wqh, 2048 * 2048 / 4);
    cvt_h<<<2048 * 512 / 4 / 256, 256>>>(Wk, wkh, 2048 * 512 / 4);
    cvt_h<<<2048 * 512 / 4 / 256, 256>>>(Wv, wvh, 2048 * 512 / 4);
    cvt_h<<<2048 * 2048 / 4 / 256, 256>>>(Wo, woh, 2048 * 2048 / 4);
    rope_table_kernel<<<BS_ * 64 / 256, 256>>>(pos);

    // 2. QKV projections (fp16 mma)
    sgemm_h<<<dim3(2048 / 128, BS_ / 128), 256, GEMM_SMEM>>>(xh, wqh, qraw, 2048, 2048);
    sgemm_h<<<dim3(512 / 128, BS_ / 128), 256, GEMM_SMEM>>>(xh, wkh, kraw, 512, 2048);
    sgemm_h<<<dim3(512 / 128, BS_ / 128), 256, GEMM_SMEM>>>(xh, wvh, vraw, 512, 2048);

    // 3. RMSNorm + RoPE + fp16 split
    {
        dim3 g(BS_, 24);
        normrope_kernel<<<g, 128>>>(qns, kns);
    }
    // 4. Attention
    {
        dim3 g(S_ / 128, B_ * H_);
        attn_mma2<<<g, 256, AT_SMEM>>>(qh, ql, kh, vh, ctxh);
    }
    // 5. Output projection
    sgemm_h<<<dim3(2048 / 128, BS_ / 128), 256, GEMM_SMEM>>>(ctxh, woh, out, 2048, 2048);
}

// round 6
// speedup vs baseline: 6.1812x; 1.0777x over previous
#include <cuda_runtime.h>
#include <cuda_fp16.h>
#include <math.h>
#include <stdint.h>

// ---------------------------------------------------------------------------
// Problem constants
// ---------------------------------------------------------------------------
#define B_   2
#define S_   2048
#define E_   2048
#define H_   16
#define KV_  4
#define D_   128
#define WIN_ 1024
#define SCALEF 0.08838834764831845f   // 1/sqrt(128)
#define BS_  (B_*S_)                   // 4096

// ---------------------------------------------------------------------------
// Scratch (static device globals)
// ---------------------------------------------------------------------------
__device__ __half g_xh[(size_t)BS_*2048];      // x fp16
__device__ __half g_wqh[(size_t)2048*2048];    // Wq fp16 [K][N]
__device__ __half g_wkvh[(size_t)2048*1024];   // [K][0:512 K-heads | 512: V-heads]
__device__ __half g_woh[(size_t)2048*2048];    // Wo fp16 [HD][E]
__device__ float g_q_raw[(size_t)BS_*2048];    // [B*S, H*D] fp32
__device__ float g_kv_raw[(size_t)BS_*1024];   // [B*S, 0:512 K | 512: V]
__device__ float2 g_tbl[(size_t)BS_*64];       // rope cos/sin table
__device__ __half g_qh[(size_t)BS_*2048];      // [B,H,S,D] fp16 hi (scaled)
__device__ __half g_ql[(size_t)BS_*2048];      // fp16 lo residual
__device__ __half g_kh[(size_t)BS_*512];       // [B,KV,S,D]
__device__ __half g_vh[(size_t)BS_*512];
__device__ __half g_ctxh[(size_t)BS_*2048];    // [B*S, H*D] fp16

// ---------------------------------------------------------------------------
// Helpers
// ---------------------------------------------------------------------------
__device__ __forceinline__ uint32_t smem_u32(const void* p) {
    uint32_t a;
    asm("{ .reg .u64 t; cvta.to.shared.u64 t, %1; cvt.u32.u64 %0, t; }"
        : "=r"(a) : "l"(p));
    return a;
}

#define CP_ASYNC16(dst_u32, gptr) \
    asm volatile("cp.async.cg.shared.global [%0], [%1], 16;" \
                 :: "r"(dst_u32), "l"(gptr) : "memory")
#define CP_COMMIT() asm volatile("cp.async.commit_group;" ::: "memory")
#define CP_WAIT1()  asm volatile("cp.async.wait_group 1;" ::: "memory")
#define CP_WAIT0()  asm volatile("cp.async.wait_group 0;" ::: "memory")

__device__ __forceinline__ void mma_f16(float* c, const uint32_t* a,
                                        const uint32_t* b) {
    asm volatile(
        "mma.sync.aligned.m16n8k16.row.col.f32.f16.f16.f32 "
        "{%0,%1,%2,%3}, {%4,%5,%6,%7}, {%8,%9}, {%0,%1,%2,%3};"
        : "+f"(c[0]), "+f"(c[1]), "+f"(c[2]), "+f"(c[3])
        : "r"(a[0]), "r"(a[1]), "r"(a[2]), "r"(a[3]), "r"(b[0]), "r"(b[1]));
}

__device__ __forceinline__ void ldsm4(uint32_t* r, uint32_t a) {
    asm volatile("ldmatrix.sync.aligned.m8n8.x4.shared.b16 {%0,%1,%2,%3}, [%4];"
        : "=r"(r[0]), "=r"(r[1]), "=r"(r[2]), "=r"(r[3]) : "r"(a));
}
__device__ __forceinline__ void ldsm4t(uint32_t* r, uint32_t a) {
    asm volatile("ldmatrix.sync.aligned.m8n8.x4.trans.shared.b16 {%0,%1,%2,%3}, [%4];"
        : "=r"(r[0]), "=r"(r[1]), "=r"(r[2]), "=r"(r[3]) : "r"(a));
}

// ---------------------------------------------------------------------------
// fp32 -> fp16 convert (vectorized)
// ---------------------------------------------------------------------------
__global__ void cvt_h(const float* __restrict__ in, __half* __restrict__ out,
                      int n4) {
    int i = blockIdx.x * blockDim.x + threadIdx.x;
    if (i < n4) {
        float4 v = ((const float4*)in)[i];
        ((__half2*)out)[i * 2]     = __floats2half2_rn(v.x, v.y);
        ((__half2*)out)[i * 2 + 1] = __floats2half2_rn(v.z, v.w);
    }
}

// Combined K|V weight convert -> g_wkvh[2048][1024]
__global__ void cvt_kv(const float* __restrict__ Wk, const float* __restrict__ Wv) {
    int i = blockIdx.x * blockDim.x + threadIdx.x;   // over 2048*1024/4
    int col4 = i & 255, row = i >> 8;
    const float* src = (col4 < 128)
        ? (Wk + (size_t)row * 512 + col4 * 4)
        : (Wv + (size_t)row * 512 + (col4 - 128) * 4);
    float4 v = *(const float4*)src;
    __half2* dst = (__half2*)(g_wkvh + (size_t)row * 1024 + col4 * 4);
    dst[0] = __floats2half2_rn(v.x, v.y);
    dst[1] = __floats2half2_rn(v.z, v.w);
}

// ---------------------------------------------------------------------------
// RoPE cos/sin table (double precision, tiny kernel)
// ---------------------------------------------------------------------------
__global__ void rope_table_kernel(const int* __restrict__ positions) {
    int idx = blockIdx.x * 256 + threadIdx.x;   // BS_*64 total
    int bs = idx >> 6, i = idx & 63;
    double ang = (double)positions[bs] * exp(-(double)i * (9.210340371976184 / 64.0));
    double sn, cs;
    sincos(ang, &sn, &cs);
    g_tbl[idx] = make_float2((float)cs, (float)sn);
}

// ---------------------------------------------------------------------------
// fp16 mma GEMM: C[M,N] = A[M,K] @ B[K,N]   (A,B fp16 row-major, C fp32)
// 128x128 CTA tile, K chunk 64, double-buffered cp.async, ldmatrix.
// 8 warps 2(m) x 4(n): warp tile 64x32. grid (N/128, M/128), 256 thr.
// smem: 2 x (A[128][72] + B[64][136]) halves = 71680 B ; 2 CTAs/SM.
// ---------------------------------------------------------------------------
#define GEMM_SMEM 71680
#define GA_STRIDE 72
#define GB_STRIDE 136
#define GBUF (9216 + 8704)   // halves per buffer

__global__ __launch_bounds__(256, 2)
void sgemm_h(const __half* __restrict__ A, const __half* __restrict__ B,
             float* __restrict__ C, int N, int K) {
    extern __shared__ __align__(16) __half smg[];
    const int tid = threadIdx.x;
    const int lane = tid & 31, w = tid >> 5;
    const int wm = (w & 1) * 64, wn = (w >> 1) * 32;
    const int m0 = blockIdx.y * 128, n0 = blockIdx.x * 128;
    const uint32_t smb = smem_u32(smg);
    const int NC = K >> 6;

#define G_LOAD(c) do {                                                        \
    const int _ko = (c) << 6;                                                 \
    const uint32_t _bb = smb + (uint32_t)(((c) & 1) * GBUF * 2);              \
    _Pragma("unroll")                                                         \
    for (int _j = 0; _j < 8; ++_j) {                                          \
        int _idx = tid + _j * 256;                                            \
        if (_idx < 1024) {                                                    \
            int _r = _idx >> 3, _seg = _idx & 7;                              \
            CP_ASYNC16(_bb + (uint32_t)((_r * GA_STRIDE + _seg * 8) * 2),     \
                       A + (size_t)(m0 + _r) * K + _ko + _seg * 8);           \
        } else {                                                              \
            int _i = _idx - 1024;                                             \
            int _r = _i >> 4, _seg = _i & 15;                                 \
            CP_ASYNC16(_bb + (uint32_t)((9216 + _r * GB_STRIDE + _seg * 8) * 2), \
                       B + (size_t)(_ko + _r) * N + n0 + _seg * 8);           \
        }                                                                     \
    }                                                                         \
    CP_COMMIT();                                                              \
} while (0)

    float acc[4][4][4];
#pragma unroll
    for (int i = 0; i < 4; ++i)
#pragma unroll
        for (int j = 0; j < 4; ++j)
#pragma unroll
            for (int k = 0; k < 4; ++k) acc[i][j][k] = 0.f;

    G_LOAD(0);

    const int a_row = (lane & 7) + ((lane >> 3) & 1) * 8;
    const int a_csel = ((lane >> 4) & 1) * 8;
    const int b_krow = ((lane >> 3) & 1) * 8 + (lane & 7);
    const int b_nsel = ((lane >> 4) & 1) * 8;

    for (int c = 0; c < NC; ++c) {
        if (c + 1 < NC) { G_LOAD(c + 1); CP_WAIT1(); }
        else CP_WAIT0();
        __syncthreads();

        const uint32_t ab = smb + (uint32_t)((c & 1) * GBUF * 2);
        const uint32_t bb = ab + 9216u * 2;
#pragma unroll
        for (int k16 = 0; k16 < 4; ++k16) {
            uint32_t af[4][4], bf[2][4];
#pragma unroll
            for (int mt = 0; mt < 4; ++mt)
                ldsm4(af[mt], ab + (uint32_t)(((wm + mt * 16 + a_row) * GA_STRIDE
                                               + k16 * 16 + a_csel) * 2));
#pragma unroll
            for (int np = 0; np < 2; ++np)
                ldsm4t(bf[np], bb + (uint32_t)(((k16 * 16 + b_krow) * GB_STRIDE
                                                + wn + np * 16 + b_nsel) * 2));
#pragma unroll
            for (int mt = 0; mt < 4; ++mt)
#pragma unroll
                for (int nt = 0; nt < 4; ++nt)
                    mma_f16(acc[mt][nt], af[mt], bf[nt >> 1] + (nt & 1) * 2);
        }
        __syncthreads();
    }

#pragma unroll
    for (int mt = 0; mt < 4; ++mt)
#pragma unroll
        for (int nt = 0; nt < 4; ++nt) {
            const int row = m0 + wm + mt * 16 + (lane >> 2);
            const int col = n0 + wn + nt * 8 + (lane & 3) * 2;
            *(float2*)&C[(size_t)row * N + col] =
                make_float2(acc[mt][nt][0], acc[mt][nt][1]);
            *(float2*)&C[(size_t)(row + 8) * N + col] =
                make_float2(acc[mt][nt][2], acc[mt][nt][3]);
        }
#undef G_LOAD
}

// ---------------------------------------------------------------------------
// RMSNorm + RoPE (table-based); emits fp16 Q hi/lo (scaled), K, V.
// grid.x = B*S, grid.y = 24, 128 threads.
// ---------------------------------------------------------------------------
__global__ void normrope_kernel(const float* __restrict__ qscale,
                                const float* __restrict__ kscale) {
    const int bs = blockIdx.x, slot = blockIdx.y, t = threadIdx.x;
    const int b = bs >> 11, s = bs & (S_ - 1);

    if (slot >= 20) {  // V
        int kvh = slot - 20;
        float v = g_kv_raw[(size_t)bs * 1024 + 512 + kvh * 128 + t];
        g_vh[((size_t)(b * KV_ + kvh) * S_ + s) * D_ + t] = __float2half_rn(v);
        return;
    }

    const float* in;
    const float* scale;
    if (slot < 16) {
        in = g_q_raw + (size_t)bs * 2048 + slot * 128;
        scale = qscale;
    } else {
        in = g_kv_raw + (size_t)bs * 1024 + (slot - 16) * 128;
        scale = kscale;
    }

    float x = in[t];
    float ss = x * x;
#pragma unroll
    for (int o = 16; o; o >>= 1) ss += __shfl_xor_sync(~0u, ss, o);
    __shared__ float wsum[4];
    __shared__ float sv[128];
    if ((t & 31) == 0) wsum[t >> 5] = ss;
    __syncthreads();
    ss = wsum[0] + wsum[1] + wsum[2] + wsum[3];
    float y = x * rsqrtf(ss * (1.0f / 128.0f) + 1e-6f) * scale[t];
    sv[t] = y;
    __syncthreads();

    float2 cssn = g_tbl[(size_t)bs * 64 + (t & 63)];
    float o;
    if (t < 64) o = y * cssn.x - sv[t + 64] * cssn.y;
    else        o = y * cssn.x + sv[t - 64] * cssn.y;

    if (slot < 16) {
        float qs = o * SCALEF;
        __half hh = __float2half_rn(qs);
        __half hl = __float2half_rn(qs - __half2float(hh));
        size_t idx = ((size_t)(b * H_ + slot) * S_ + s) * D_ + t;
        g_qh[idx] = hh;
        g_ql[idx] = hl;
    } else {
        size_t idx = ((size_t)(b * KV_ + (slot - 16)) * S_ + s) * D_ + t;
        g_kh[idx] = __float2half_rn(o);
    }
}

// ---------------------------------------------------------------------------
// Tensor-core windowed flash attention v3.
// BM=128, BN=128. Q hi/lo smem (loaded once), K/V double-buffered,
// P in registers, single-fp16 P (no lo-compensation in PV).
// grid (S/128 reversed, B*H), 256 threads (8 warps x 16 q-rows).
// smem halves: QH 0, QL 17408, K0 34816, K1 52224, V0 69632, V1 87040
// ---------------------------------------------------------------------------
#define AT_SMEM 208896
#define OQH 0
#define OQL 17408
#define OK0 34816
#define OK1 52224
#define OV0 69632
#define OV1 87040

__global__ __launch_bounds__(256, 1)
void attn_mma2(const __half* __restrict__ Qh, const __half* __restrict__ Ql,
               const __half* __restrict__ Kh, const __half* __restrict__ Vh,
               __half* __restrict__ ctx) {
    extern __shared__ __align__(16) __half smh[];
    const int tid = threadIdx.x, lane = tid & 31, w = tid >> 5;
    const int qt = gridDim.x - 1 - blockIdx.x;     // long blocks first
    const int q0 = qt * 128;
    const int bh = blockIdx.y, b = bh >> 4, h = bh & 15, kvh = (h & 15) >> 2;
    const __half* qhp = Qh + ((size_t)bh * S_ + q0) * D_;
    const __half* qlp = Ql + ((size_t)bh * S_ + q0) * D_;
    const __half* kp = Kh + (size_t)(b * KV_ + kvh) * S_ * D_;
    const __half* vp = Vh + (size_t)(b * KV_ + kvh) * S_ * D_;
    const uint32_t smb = smem_u32(smh);

#pragma unroll
    for (int j = 0; j < 16; ++j) {
        int idx = tid + j * 256;
        int which = idx >> 11;
        int r = (idx >> 4) & 127;
        int seg = idx & 15;
        const __half* src = (which ? qlp : qhp) + r * 128 + seg * 8;
        uint32_t dst = smb + (uint32_t)(((which ? OQL : OQH) + r * 136 + seg * 8) * 2);
        CP_ASYNC16(dst, src);
    }

    int jt0 = q0 - (WIN_ - 1);
    if (jt0 < 0) jt0 = 0;
    jt0 &= ~127;
    const int ntl = (q0 + 128 - jt0) >> 7;

#define LOAD_KV(jt, kb, vb) do {                                              \
    _Pragma("unroll")                                                         \
    for (int _j = 0; _j < 16; ++_j) {                                         \
        int _idx = tid + _j * 256;                                            \
        int _wh = _idx >> 11;                                                 \
        int _r = (_idx >> 4) & 127;                                           \
        int _seg = _idx & 15;                                                 \
        const __half* _src = (_wh ? vp : kp) + (size_t)((jt) + _r) * 128 + _seg * 8; \
        uint32_t _dst = smb + (uint32_t)((((_wh) ? (vb) : (kb)) + _r * 136 + _seg * 8) * 2); \
        CP_ASYNC16(_dst, _src);                                               \
    }                                                                         \
} while (0)

    LOAD_KV(jt0, OK0, OV0);
    CP_COMMIT();

    float acc[16][4];
#pragma unroll
    for (int i = 0; i < 16; ++i)
#pragma unroll
        for (int j = 0; j < 4; ++j) acc[i][j] = 0.f;
    float mrow0 = -1e30f, mrow1 = -1e30f, lrow0 = 0.f, lrow1 = 0.f;

    const int m0w = w * 16;
    const int a_row = m0w + (lane & 7) + ((lane >> 3) & 1) * 8;
    const int a_col = ((lane >> 4) & 1) * 8;
    const uint32_t aqh = smb + (uint32_t)((OQH + a_row * 136 + a_col) * 2);
    const uint32_t aql = smb + (uint32_t)((OQL + a_row * 136 + a_col) * 2);
    const int k_off = ((((lane >> 4) & 1) * 8 + (lane & 7)) * 136
                       + ((lane >> 3) & 1) * 8) * 2;
    const int v_row = ((lane >> 3) & 1) * 8 + (lane & 7);
    const int v_csel = ((lane >> 4) & 1) * 8;

    for (int it = 0; it < ntl; ++it) {
        const int jt = jt0 + it * 128;
        __syncthreads();
        if (it + 1 < ntl) {
            LOAD_KV(jt + 128, ((it + 1) & 1) ? OK1 : OK0,
                    ((it + 1) & 1) ? OV1 : OV0);
            CP_COMMIT();
            CP_WAIT1();
        } else {
            CP_COMMIT();
            CP_WAIT0();
        }
        __syncthreads();

        const uint32_t kbase = smb + (uint32_t)(((it & 1) ? OK1 : OK0) * 2);
        const uint32_t vbase = smb + (uint32_t)(((it & 1) ? OV1 : OV0) * 2);

        // ---- S = (Qh + Ql) K^T ----
        float sf[16][4];
#pragma unroll
        for (int i = 0; i < 16; ++i)
#pragma unroll
            for (int j = 0; j < 4; ++j) sf[i][j] = 0.f;

#pragma unroll
        for (int k16 = 0; k16 < 8; ++k16) {
            uint32_t ah[4], al[4];
            ldsm4(ah, aqh + k16 * 32);
            ldsm4(al, aql + k16 * 32);
#pragma unroll
            for (int p = 0; p < 8; ++p) {
                uint32_t bb[4];
                ldsm4(bb, kbase + (uint32_t)(k_off + (p * 16 * 136 + k16 * 16) * 2));
                mma_f16(sf[2 * p],     ah, bb);
                mma_f16(sf[2 * p],     al, bb);
                mma_f16(sf[2 * p + 1], ah, bb + 2);
                mma_f16(sf[2 * p + 1], al, bb + 2);
            }
        }

        // ---- softcap + mask + online softmax ----
        const int r0 = q0 + m0w + (lane >> 2);
        const int r1 = r0 + 8;
        const int cb = jt + (lane & 3) * 2;
        const bool need_mask = (jt + 127 > q0 + m0w) ||
                               (jt < q0 + m0w + 15 - (WIN_ - 1));
        float mx0 = -1e30f, mx1 = -1e30f;
#pragma unroll
        for (int nt = 0; nt < 16; ++nt) {
#pragma unroll
            for (int e = 0; e < 2; ++e) {
                const int col = cb + nt * 8 + e;
                {
                    float v = sf[nt][e];
                    float z = __expf(v * 0.04f);
                    float tt = 50.f - __fdividef(100.f, z + 1.f);
                    bool ok = !need_mask || ((col <= r0) && (r0 - col < WIN_));
                    v = ok ? tt : -1e30f;
                    sf[nt][e] = v;
                    mx0 = fmaxf(mx0, v);
                }
                {
                    float v = sf[nt][2 + e];
                    float z = __expf(v * 0.04f);
                    float tt = 50.f - __fdividef(100.f, z + 1.f);
                    bool ok = !need_mask || ((col <= r1) && (r1 - col < WIN_));
                    v = ok ? tt : -1e30f;
                    sf[nt][2 + e] = v;
                    mx1 = fmaxf(mx1, v);
                }
            }
        }
        mx0 = fmaxf(mx0, __shfl_xor_sync(~0u, mx0, 1));
        mx0 = fmaxf(mx0, __shfl_xor_sync(~0u, mx0, 2));
        mx1 = fmaxf(mx1, __shfl_xor_sync(~0u, mx1, 1));
        mx1 = fmaxf(mx1, __shfl_xor_sync(~0u, mx1, 2));
        const float mn0 = fmaxf(mrow0, mx0), mn1 = fmaxf(mrow1, mx1);
        const float al0 = __expf(mrow0 - mn0), al1 = __expf(mrow1 - mn1);
        mrow0 = mn0; mrow1 = mn1;

        float s0 = 0.f, s1 = 0.f;
#pragma unroll
        for (int nt = 0; nt < 16; ++nt) {
            float p0 = (sf[nt][0] > -1e29f) ? __expf(sf[nt][0] - mn0) : 0.f;
            float p1 = (sf[nt][1] > -1e29f) ? __expf(sf[nt][1] - mn0) : 0.f;
            float p2 = (sf[nt][2] > -1e29f) ? __expf(sf[nt][2] - mn1) : 0.f;
            float p3 = (sf[nt][3] > -1e29f) ? __expf(sf[nt][3] - mn1) : 0.f;
            s0 += p0 + p1; s1 += p2 + p3;
            sf[nt][0] = p0; sf[nt][1] = p1; sf[nt][2] = p2; sf[nt][3] = p3;
        }
        s0 += __shfl_xor_sync(~0u, s0, 1);
        s0 += __shfl_xor_sync(~0u, s0, 2);
        s1 += __shfl_xor_sync(~0u, s1, 1);
        s1 += __shfl_xor_sync(~0u, s1, 2);
        lrow0 = lrow0 * al0 + s0;
        lrow1 = lrow1 * al1 + s1;
#pragma unroll
        for (int nt = 0; nt < 16; ++nt) {
            acc[nt][0] *= al0; acc[nt][1] *= al0;
            acc[nt][2] *= al1; acc[nt][3] *= al1;
        }

        // ---- O += P V  (P single fp16, in registers) ----
#pragma unroll
        for (int k16 = 0; k16 < 8; ++k16) {
            const float* pa = sf[2 * k16];
            const float* pb = sf[2 * k16 + 1];
            uint32_t PH[4];
            {
                __half2 h0 = __floats2half2_rn(pa[0], pa[1]);
                __half2 h1 = __floats2half2_rn(pa[2], pa[3]);
                __half2 h2 = __floats2half2_rn(pb[0], pb[1]);
                __half2 h3 = __floats2half2_rn(pb[2], pb[3]);
                PH[0] = *(uint32_t*)&h0; PH[1] = *(uint32_t*)&h1;
                PH[2] = *(uint32_t*)&h2; PH[3] = *(uint32_t*)&h3;
            }
#pragma unroll
            for (int p = 0; p < 8; ++p) {
                uint32_t bb[4];
                ldsm4t(bb, vbase + (uint32_t)(((k16 * 16 + v_row) * 136
                                               + p * 16 + v_csel) * 2));
                mma_f16(acc[2 * p],     PH, bb);
                mma_f16(acc[2 * p + 1], PH, bb + 2);
            }
        }
    }

    // epilogue
    const float i0 = 1.f / lrow0, i1 = 1.f / lrow1;
    const int row0 = q0 + m0w + (lane >> 2);
    __half* c0 = ctx + ((size_t)(b * S_ + row0) * H_ + h) * D_ + (lane & 3) * 2;
    __half* c1 = c0 + (size_t)8 * H_ * D_;
#pragma unroll
    for (int nt = 0; nt < 16; ++nt) {
        *(__half2*)(c0 + nt * 8) = __floats2half2_rn(acc[nt][0] * i0, acc[nt][1] * i0);
        *(__half2*)(c1 + nt * 8) = __floats2half2_rn(acc[nt][2] * i1, acc[nt][3] * i1);
    }
#undef LOAD_KV
}

// ---------------------------------------------------------------------------
// kernel_launch
// inputs: 0:x 1:positions 2:mask(unused) 3:Wq 4:Wk 5:Wv 6:Wo 7:q_norm 8:k_norm
// ---------------------------------------------------------------------------
extern "C" void kernel_launch(void* const* d_in, const int* in_sizes, int n_in,
                              void* d_out, int out_size) {
    (void)in_sizes; (void)n_in; (void)out_size;
    const float* x   = (const float*)d_in[0];
    const int* pos   = (const int*)d_in[1];
    const float* Wq  = (const float*)d_in[3];
    const float* Wk  = (const float*)d_in[4];
    const float* Wv  = (const float*)d_in[5];
    const float* Wo  = (const float*)d_in[6];
    const float* qns = (const float*)d_in[7];
    const float* kns = (const float*)d_in[8];
    float* out = (float*)d_out;

    __half *xh, *wqh, *wkvh, *woh, *qh, *ql, *kh, *vh, *ctxh;
    float *qraw, *kvraw;
    cudaGetSymbolAddress((void**)&xh,   g_xh);
    cudaGetSymbolAddress((void**)&wqh,  g_wqh);
    cudaGetSymbolAddress((void**)&wkvh, g_wkvh);
    cudaGetSymbolAddress((void**)&woh,  g_woh);
    cudaGetSymbolAddress((void**)&qraw, g_q_raw);
    cudaGetSymbolAddress((void**)&kvraw, g_kv_raw);
    cudaGetSymbolAddress((void**)&qh, g_qh);
    cudaGetSymbolAddress((void**)&ql, g_ql);
    cudaGetSymbolAddress((void**)&kh, g_kh);
    cudaGetSymbolAddress((void**)&vh, g_vh);
    cudaGetSymbolAddress((void**)&ctxh, g_ctxh);

    cudaFuncSetAttribute(sgemm_h,
                         cudaFuncAttributeMaxDynamicSharedMemorySize, GEMM_SMEM);
    cudaFuncSetAttribute(attn_mma2,
                         cudaFuncAttributeMaxDynamicSharedMemorySize, AT_SMEM);

    // 1. fp16 converts + rope table
    cvt_h<<<BS_ * 2048 / 4 / 256, 256>>>(x, xh, BS_ * 2048 / 4);
    cvt_h<<<2048 * 2048 / 4 / 256, 256>>>(Wq, wqh, 2048 * 2048 / 4);
    cvt_kv<<<2048 * 1024 / 4 / 256, 256>>>(Wk, Wv);
    cvt_h<<<2048 * 2048 / 4 / 256, 256>>>(Wo, woh, 2048 * 2048 / 4);
    rope_table_kernel<<<BS_ * 64 / 256, 256>>>(pos);

    // 2. Q and fused K|V projections (fp16 mma)
    sgemm_h<<<dim3(2048 / 128, BS_ / 128), 256, GEMM_SMEM>>>(xh, wqh, qraw, 2048, 2048);
    sgemm_h<<<dim3(1024 / 128, BS_ / 128), 256, GEMM_SMEM>>>(xh, wkvh, kvraw, 1024, 2048);

    // 3. RMSNorm + RoPE + fp16 split
    {
        dim3 g(BS_, 24);
        normrope_kernel<<<g, 128>>>(qns, kns);
    }
    // 4. Attention
    {
        dim3 g(S_ / 128, B_ * H_);
        attn_mma2<<<g, 256, AT_SMEM>>>(qh, ql, kh, vh, ctxh);
    }
    // 5. Output projection
    sgemm_h<<<dim3(2048 / 128, BS_ / 128), 256, GEMM_SMEM>>>(ctxh, woh, out, 2048, 2048);
}

// round 7
// speedup vs baseline: 6.3630x; 1.0294x over previous
#include <cuda_runtime.h>
#include <cuda_fp16.h>
#include <math.h>
#include <stdint.h>

// ---------------------------------------------------------------------------
// Problem constants
// ---------------------------------------------------------------------------
#define B_   2
#define S_   2048
#define E_   2048
#define H_   16
#define KV_  4
#define D_   128
#define WIN_ 1024
#define SCALEF 0.08838834764831845f   // 1/sqrt(128)
#define BS_  (B_*S_)                   // 4096

// ---------------------------------------------------------------------------
// Scratch (static device globals)
// ---------------------------------------------------------------------------
__device__ __half g_xh[(size_t)BS_*2048];      // x fp16
__device__ __half g_wqh[(size_t)2048*2048];    // Wq fp16 [K][N]
__device__ __half g_wkvh[(size_t)2048*1024];   // [K][0:512 K | 512: V]
__device__ __half g_woh[(size_t)2048*2048];    // Wo fp16 [HD][E]
__device__ float g_q_raw[(size_t)BS_*2048];    // [B*S, H*D] fp32
__device__ float g_kv_raw[(size_t)BS_*1024];   // [B*S, 0:512 K | 512: V]
__device__ float2 g_tbl[(size_t)BS_*64];       // rope cos/sin table
__device__ __half g_qh[(size_t)BS_*2048];      // [B,H,S,D] fp16 (scaled)
__device__ __half g_kh[(size_t)BS_*512];       // [B,KV,S,D]
__device__ __half g_vh[(size_t)BS_*512];
__device__ __half g_ctxh[(size_t)BS_*2048];    // [B*S, H*D] fp16

// ---------------------------------------------------------------------------
// Helpers
// ---------------------------------------------------------------------------
__device__ __forceinline__ uint32_t smem_u32(const void* p) {
    uint32_t a;
    asm("{ .reg .u64 t; cvta.to.shared.u64 t, %1; cvt.u32.u64 %0, t; }"
        : "=r"(a) : "l"(p));
    return a;
}

#define CP_ASYNC16(dst_u32, gptr) \
    asm volatile("cp.async.cg.shared.global [%0], [%1], 16;" \
                 :: "r"(dst_u32), "l"(gptr) : "memory")
#define CP_COMMIT() asm volatile("cp.async.commit_group;" ::: "memory")
#define CP_WAIT1()  asm volatile("cp.async.wait_group 1;" ::: "memory")
#define CP_WAIT0()  asm volatile("cp.async.wait_group 0;" ::: "memory")

__device__ __forceinline__ void mma_f16(float* c, const uint32_t* a,
                                        const uint32_t* b) {
    asm volatile(
        "mma.sync.aligned.m16n8k16.row.col.f32.f16.f16.f32 "
        "{%0,%1,%2,%3}, {%4,%5,%6,%7}, {%8,%9}, {%0,%1,%2,%3};"
        : "+f"(c[0]), "+f"(c[1]), "+f"(c[2]), "+f"(c[3])
        : "r"(a[0]), "r"(a[1]), "r"(a[2]), "r"(a[3]), "r"(b[0]), "r"(b[1]));
}

__device__ __forceinline__ void ldsm4(uint32_t* r, uint32_t a) {
    asm volatile("ldmatrix.sync.aligned.m8n8.x4.shared.b16 {%0,%1,%2,%3}, [%4];"
        : "=r"(r[0]), "=r"(r[1]), "=r"(r[2]), "=r"(r[3]) : "r"(a));
}
__device__ __forceinline__ void ldsm4t(uint32_t* r, uint32_t a) {
    asm volatile("ldmatrix.sync.aligned.m8n8.x4.trans.shared.b16 {%0,%1,%2,%3}, [%4];"
        : "=r"(r[0]), "=r"(r[1]), "=r"(r[2]), "=r"(r[3]) : "r"(a));
}

// Padé(5,4) tanh softcap: tt = 50*tanh(v/50), exact to ~1e-9 for |v|<=11.4
__device__ __forceinline__ float softcap(float v) {
    float u2 = v * v * 4e-4f;
    float num = fmaf(u2, 105.f + u2, 945.f);
    float den = fmaf(u2, fmaf(15.f, u2, 420.f), 945.f);
    return v * __fdividef(num, den);
}

// ---------------------------------------------------------------------------
// fp32 -> fp16 convert, ILP-4 grid-stride
// ---------------------------------------------------------------------------
__global__ void cvt_h(const float* __restrict__ in, __half* __restrict__ out,
                      int n4) {
    int base = blockIdx.x * blockDim.x * 4 + threadIdx.x;
#pragma unroll
    for (int j = 0; j < 4; ++j) {
        int i = base + j * blockDim.x;
        if (i < n4) {
            float4 v = ((const float4*)in)[i];
            ((__half2*)out)[i * 2]     = __floats2half2_rn(v.x, v.y);
            ((__half2*)out)[i * 2 + 1] = __floats2half2_rn(v.z, v.w);
        }
    }
}

// Combined K|V weight convert -> g_wkvh[2048][1024], ILP-4
__global__ void cvt_kv(const float* __restrict__ Wk, const float* __restrict__ Wv) {
    int base = blockIdx.x * blockDim.x * 4 + threadIdx.x;
#pragma unroll
    for (int j = 0; j < 4; ++j) {
        int i = base + j * blockDim.x;     // over 2048*1024/4
        int col4 = i & 255, row = i >> 8;
        const float* src = (col4 < 128)
            ? (Wk + (size_t)row * 512 + col4 * 4)
            : (Wv + (size_t)row * 512 + (col4 - 128) * 4);
        float4 v = *(const float4*)src;
        __half2* dst = (__half2*)(g_wkvh + (size_t)row * 1024 + col4 * 4);
        dst[0] = __floats2half2_rn(v.x, v.y);
        dst[1] = __floats2half2_rn(v.z, v.w);
    }
}

// ---------------------------------------------------------------------------
// RoPE cos/sin table (double precision, tiny kernel)
// ---------------------------------------------------------------------------
__global__ void rope_table_kernel(const int* __restrict__ positions) {
    int idx = blockIdx.x * 256 + threadIdx.x;   // BS_*64 total
    int bs = idx >> 6, i = idx & 63;
    double ang = (double)positions[bs] * exp(-(double)i * (9.210340371976184 / 64.0));
    double sn, cs;
    sincos(ang, &sn, &cs);
    g_tbl[idx] = make_float2((float)cs, (float)sn);
}

// ---------------------------------------------------------------------------
// fp16 mma GEMM: C[M,N] = A[M,K] @ B[K,N]  (unchanged from R6)
// ---------------------------------------------------------------------------
#define GEMM_SMEM 71680
#define GA_STRIDE 72
#define GB_STRIDE 136
#define GBUF (9216 + 8704)

__global__ __launch_bounds__(256, 2)
void sgemm_h(const __half* __restrict__ A, const __half* __restrict__ B,
             float* __restrict__ C, int N, int K) {
    extern __shared__ __align__(16) __half smg[];
    const int tid = threadIdx.x;
    const int lane = tid & 31, w = tid >> 5;
    const int wm = (w & 1) * 64, wn = (w >> 1) * 32;
    const int m0 = blockIdx.y * 128, n0 = blockIdx.x * 128;
    const uint32_t smb = smem_u32(smg);
    const int NC = K >> 6;

#define G_LOAD(c) do {                                                        \
    const int _ko = (c) << 6;                                                 \
    const uint32_t _bb = smb + (uint32_t)(((c) & 1) * GBUF * 2);              \
    _Pragma("unroll")                                                         \
    for (int _j = 0; _j < 8; ++_j) {                                          \
        int _idx = tid + _j * 256;                                            \
        if (_idx < 1024) {                                                    \
            int _r = _idx >> 3, _seg = _idx & 7;                              \
            CP_ASYNC16(_bb + (uint32_t)((_r * GA_STRIDE + _seg * 8) * 2),     \
                       A + (size_t)(m0 + _r) * K + _ko + _seg * 8);           \
        } else {                                                              \
            int _i = _idx - 1024;                                             \
            int _r = _i >> 4, _seg = _i & 15;                                 \
            CP_ASYNC16(_bb + (uint32_t)((9216 + _r * GB_STRIDE + _seg * 8) * 2), \
                       B + (size_t)(_ko + _r) * N + n0 + _seg * 8);           \
        }                                                                     \
    }                                                                         \
    CP_COMMIT();                                                              \
} while (0)

    float acc[4][4][4];
#pragma unroll
    for (int i = 0; i < 4; ++i)
#pragma unroll
        for (int j = 0; j < 4; ++j)
#pragma unroll
            for (int k = 0; k < 4; ++k) acc[i][j][k] = 0.f;

    G_LOAD(0);

    const int a_row = (lane & 7) + ((lane >> 3) & 1) * 8;
    const int a_csel = ((lane >> 4) & 1) * 8;
    const int b_krow = ((lane >> 3) & 1) * 8 + (lane & 7);
    const int b_nsel = ((lane >> 4) & 1) * 8;

    for (int c = 0; c < NC; ++c) {
        if (c + 1 < NC) { G_LOAD(c + 1); CP_WAIT1(); }
        else CP_WAIT0();
        __syncthreads();

        const uint32_t ab = smb + (uint32_t)((c & 1) * GBUF * 2);
        const uint32_t bb = ab + 9216u * 2;
#pragma unroll
        for (int k16 = 0; k16 < 4; ++k16) {
            uint32_t af[4][4], bf[2][4];
#pragma unroll
            for (int mt = 0; mt < 4; ++mt)
                ldsm4(af[mt], ab + (uint32_t)(((wm + mt * 16 + a_row) * GA_STRIDE
                                               + k16 * 16 + a_csel) * 2));
#pragma unroll
            for (int np = 0; np < 2; ++np)
                ldsm4t(bf[np], bb + (uint32_t)(((k16 * 16 + b_krow) * GB_STRIDE
                                                + wn + np * 16 + b_nsel) * 2));
#pragma unroll
            for (int mt = 0; mt < 4; ++mt)
#pragma unroll
                for (int nt = 0; nt < 4; ++nt)
                    mma_f16(acc[mt][nt], af[mt], bf[nt >> 1] + (nt & 1) * 2);
        }
        __syncthreads();
    }

#pragma unroll
    for (int mt = 0; mt < 4; ++mt)
#pragma unroll
        for (int nt = 0; nt < 4; ++nt) {
            const int row = m0 + wm + mt * 16 + (lane >> 2);
            const int col = n0 + wn + nt * 8 + (lane & 3) * 2;
            *(float2*)&C[(size_t)row * N + col] =
                make_float2(acc[mt][nt][0], acc[mt][nt][1]);
            *(float2*)&C[(size_t)(row + 8) * N + col] =
                make_float2(acc[mt][nt][2], acc[mt][nt][3]);
        }
#undef G_LOAD
}

// ---------------------------------------------------------------------------
// RMSNorm + RoPE (table-based); emits fp16 Q (scaled), K, V.
// ---------------------------------------------------------------------------
__global__ void normrope_kernel(const float* __restrict__ qscale,
                                const float* __restrict__ kscale) {
    const int bs = blockIdx.x, slot = blockIdx.y, t = threadIdx.x;
    const int b = bs >> 11, s = bs & (S_ - 1);

    if (slot >= 20) {  // V
        int kvh = slot - 20;
        float v = g_kv_raw[(size_t)bs * 1024 + 512 + kvh * 128 + t];
        g_vh[((size_t)(b * KV_ + kvh) * S_ + s) * D_ + t] = __float2half_rn(v);
        return;
    }

    const float* in;
    const float* scale;
    if (slot < 16) {
        in = g_q_raw + (size_t)bs * 2048 + slot * 128;
        scale = qscale;
    } else {
        in = g_kv_raw + (size_t)bs * 1024 + (slot - 16) * 128;
        scale = kscale;
    }

    float x = in[t];
    float ss = x * x;
#pragma unroll
    for (int o = 16; o; o >>= 1) ss += __shfl_xor_sync(~0u, ss, o);
    __shared__ float wsum[4];
    __shared__ float sv[128];
    if ((t & 31) == 0) wsum[t >> 5] = ss;
    __syncthreads();
    ss = wsum[0] + wsum[1] + wsum[2] + wsum[3];
    float y = x * rsqrtf(ss * (1.0f / 128.0f) + 1e-6f) * scale[t];
    sv[t] = y;
    __syncthreads();

    float2 cssn = g_tbl[(size_t)bs * 64 + (t & 63)];
    float o;
    if (t < 64) o = y * cssn.x - sv[t + 64] * cssn.y;
    else        o = y * cssn.x + sv[t - 64] * cssn.y;

    if (slot < 16) {
        size_t idx = ((size_t)(b * H_ + slot) * S_ + s) * D_ + t;
        g_qh[idx] = __float2half_rn(o * SCALEF);
    } else {
        size_t idx = ((size_t)(b * KV_ + (slot - 16)) * S_ + s) * D_ + t;
        g_kh[idx] = __float2half_rn(o);
    }
}

// ---------------------------------------------------------------------------
// Tensor-core windowed flash attention v4.
// BM=128, BN=128. Single-fp16 Q (smem, loaded once), K/V double-buffered,
// P in registers single-fp16, Padé softcap.
// smem halves: QH 0, K0 17408, K1 34816, V0 52224, V1 69632 -> 87040 halves
// ---------------------------------------------------------------------------
#define AT_SMEM 174080
#define OQH 0
#define OK0 17408
#define OK1 34816
#define OV0 52224
#define OV1 69632

__global__ __launch_bounds__(256, 1)
void attn_mma2(const __half* __restrict__ Qh, const __half* __restrict__ Kh,
               const __half* __restrict__ Vh, __half* __restrict__ ctx) {
    extern __shared__ __align__(16) __half smh[];
    const int tid = threadIdx.x, lane = tid & 31, w = tid >> 5;
    const int qt = gridDim.x - 1 - blockIdx.x;     // long blocks first
    const int q0 = qt * 128;
    const int bh = blockIdx.y, b = bh >> 4, h = bh & 15, kvh = (h & 15) >> 2;
    const __half* qhp = Qh + ((size_t)bh * S_ + q0) * D_;
    const __half* kp = Kh + (size_t)(b * KV_ + kvh) * S_ * D_;
    const __half* vp = Vh + (size_t)(b * KV_ + kvh) * S_ * D_;
    const uint32_t smb = smem_u32(smh);

    // Q: 2048 x 16B chunks, 8 per thread
#pragma unroll
    for (int j = 0; j < 8; ++j) {
        int idx = tid + j * 256;
        int r = idx >> 4, seg = idx & 15;
        CP_ASYNC16(smb + (uint32_t)((OQH + r * 136 + seg * 8) * 2),
                   qhp + r * 128 + seg * 8);
    }

    int jt0 = q0 - (WIN_ - 1);
    if (jt0 < 0) jt0 = 0;
    jt0 &= ~127;
    const int ntl = (q0 + 128 - jt0) >> 7;

#define LOAD_KV(jt, kb, vb) do {                                              \
    _Pragma("unroll")                                                         \
    for (int _j = 0; _j < 16; ++_j) {                                         \
        int _idx = tid + _j * 256;                                            \
        int _wh = _idx >> 11;                                                 \
        int _r = (_idx >> 4) & 127;                                           \
        int _seg = _idx & 15;                                                 \
        const __half* _src = (_wh ? vp : kp) + (size_t)((jt) + _r) * 128 + _seg * 8; \
        uint32_t _dst = smb + (uint32_t)((((_wh) ? (vb) : (kb)) + _r * 136 + _seg * 8) * 2); \
        CP_ASYNC16(_dst, _src);                                               \
    }                                                                         \
} while (0)

    LOAD_KV(jt0, OK0, OV0);
    CP_COMMIT();

    float acc[16][4];
#pragma unroll
    for (int i = 0; i < 16; ++i)
#pragma unroll
        for (int j = 0; j < 4; ++j) acc[i][j] = 0.f;
    float mrow0 = -1e30f, mrow1 = -1e30f, lrow0 = 0.f, lrow1 = 0.f;

    const int m0w = w * 16;
    const int a_row = m0w + (lane & 7) + ((lane >> 3) & 1) * 8;
    const int a_col = ((lane >> 4) & 1) * 8;
    const uint32_t aqh = smb + (uint32_t)((OQH + a_row * 136 + a_col) * 2);
    const int k_off = ((((lane >> 4) & 1) * 8 + (lane & 7)) * 136
                       + ((lane >> 3) & 1) * 8) * 2;
    const int v_row = ((lane >> 3) & 1) * 8 + (lane & 7);
    const int v_csel = ((lane >> 4) & 1) * 8;

    for (int it = 0; it < ntl; ++it) {
        const int jt = jt0 + it * 128;
        __syncthreads();
        if (it + 1 < ntl) {
            LOAD_KV(jt + 128, ((it + 1) & 1) ? OK1 : OK0,
                    ((it + 1) & 1) ? OV1 : OV0);
            CP_COMMIT();
            CP_WAIT1();
        } else {
            CP_COMMIT();
            CP_WAIT0();
        }
        __syncthreads();

        const uint32_t kbase = smb + (uint32_t)(((it & 1) ? OK1 : OK0) * 2);
        const uint32_t vbase = smb + (uint32_t)(((it & 1) ? OV1 : OV0) * 2);

        // ---- S = Q K^T ----
        float sf[16][4];
#pragma unroll
        for (int i = 0; i < 16; ++i)
#pragma unroll
            for (int j = 0; j < 4; ++j) sf[i][j] = 0.f;

#pragma unroll
        for (int k16 = 0; k16 < 8; ++k16) {
            uint32_t ah[4];
            ldsm4(ah, aqh + k16 * 32);
#pragma unroll
            for (int p = 0; p < 8; ++p) {
                uint32_t bb[4];
                ldsm4(bb, kbase + (uint32_t)(k_off + (p * 16 * 136 + k16 * 16) * 2));
                mma_f16(sf[2 * p],     ah, bb);
                mma_f16(sf[2 * p + 1], ah, bb + 2);
            }
        }

        // ---- Padé softcap + mask + online softmax ----
        const int r0 = q0 + m0w + (lane >> 2);
        const int r1 = r0 + 8;
        const int cb = jt + (lane & 3) * 2;
        const bool need_mask = (jt + 127 > q0 + m0w) ||
                               (jt < q0 + m0w + 15 - (WIN_ - 1));
        float mx0 = -1e30f, mx1 = -1e30f;
#pragma unroll
        for (int nt = 0; nt < 16; ++nt) {
#pragma unroll
            for (int e = 0; e < 2; ++e) {
                const int col = cb + nt * 8 + e;
                {
                    float tt = softcap(sf[nt][e]);
                    bool ok = !need_mask || ((col <= r0) && (r0 - col < WIN_));
                    tt = ok ? tt : -1e30f;
                    sf[nt][e] = tt;
                    mx0 = fmaxf(mx0, tt);
                }
                {
                    float tt = softcap(sf[nt][2 + e]);
                    bool ok = !need_mask || ((col <= r1) && (r1 - col < WIN_));
                    tt = ok ? tt : -1e30f;
                    sf[nt][2 + e] = tt;
                    mx1 = fmaxf(mx1, tt);
                }
            }
        }
        mx0 = fmaxf(mx0, __shfl_xor_sync(~0u, mx0, 1));
        mx0 = fmaxf(mx0, __shfl_xor_sync(~0u, mx0, 2));
        mx1 = fmaxf(mx1, __shfl_xor_sync(~0u, mx1, 1));
        mx1 = fmaxf(mx1, __shfl_xor_sync(~0u, mx1, 2));
        const float mn0 = fmaxf(mrow0, mx0), mn1 = fmaxf(mrow1, mx1);
        const float al0 = __expf(mrow0 - mn0), al1 = __expf(mrow1 - mn1);
        mrow0 = mn0; mrow1 = mn1;

        float s0 = 0.f, s1 = 0.f;
#pragma unroll
        for (int nt = 0; nt < 16; ++nt) {
            float p0 = (sf[nt][0] > -1e29f) ? __expf(sf[nt][0] - mn0) : 0.f;
            float p1 = (sf[nt][1] > -1e29f) ? __expf(sf[nt][1] - mn0) : 0.f;
            float p2 = (sf[nt][2] > -1e29f) ? __expf(sf[nt][2] - mn1) : 0.f;
            float p3 = (sf[nt][3] > -1e29f) ? __expf(sf[nt][3] - mn1) : 0.f;
            s0 += p0 + p1; s1 += p2 + p3;
            sf[nt][0] = p0; sf[nt][1] = p1; sf[nt][2] = p2; sf[nt][3] = p3;
        }
        s0 += __shfl_xor_sync(~0u, s0, 1);
        s0 += __shfl_xor_sync(~0u, s0, 2);
        s1 += __shfl_xor_sync(~0u, s1, 1);
        s1 += __shfl_xor_sync(~0u, s1, 2);
        lrow0 = lrow0 * al0 + s0;
        lrow1 = lrow1 * al1 + s1;
#pragma unroll
        for (int nt = 0; nt < 16; ++nt) {
            acc[nt][0] *= al0; acc[nt][1] *= al0;
            acc[nt][2] *= al1; acc[nt][3] *= al1;
        }

        // ---- O += P V ----
#pragma unroll
        for (int k16 = 0; k16 < 8; ++k16) {
            const float* pa = sf[2 * k16];
            const float* pb = sf[2 * k16 + 1];
            uint32_t PH[4];
            {
                __half2 h0 = __floats2half2_rn(pa[0], pa[1]);
                __half2 h1 = __floats2half2_rn(pa[2], pa[3]);
                __half2 h2 = __floats2half2_rn(pb[0], pb[1]);
                __half2 h3 = __floats2half2_rn(pb[2], pb[3]);
                PH[0] = *(uint32_t*)&h0; PH[1] = *(uint32_t*)&h1;
                PH[2] = *(uint32_t*)&h2; PH[3] = *(uint32_t*)&h3;
            }
#pragma unroll
            for (int p = 0; p < 8; ++p) {
                uint32_t bb[4];
                ldsm4t(bb, vbase + (uint32_t)(((k16 * 16 + v_row) * 136
                                               + p * 16 + v_csel) * 2));
                mma_f16(acc[2 * p],     PH, bb);
                mma_f16(acc[2 * p + 1], PH, bb + 2);
            }
        }
    }

    // epilogue
    const float i0 = 1.f / lrow0, i1 = 1.f / lrow1;
    const int row0 = q0 + m0w + (lane >> 2);
    __half* c0 = ctx + ((size_t)(b * S_ + row0) * H_ + h) * D_ + (lane & 3) * 2;
    __half* c1 = c0 + (size_t)8 * H_ * D_;
#pragma unroll
    for (int nt = 0; nt < 16; ++nt) {
        *(__half2*)(c0 + nt * 8) = __floats2half2_rn(acc[nt][0] * i0, acc[nt][1] * i0);
        *(__half2*)(c1 + nt * 8) = __floats2half2_rn(acc[nt][2] * i1, acc[nt][3] * i1);
    }
#undef LOAD_KV
}

// ---------------------------------------------------------------------------
// kernel_launch
// inputs: 0:x 1:positions 2:mask(unused) 3:Wq 4:Wk 5:Wv 6:Wo 7:q_norm 8:k_norm
// ---------------------------------------------------------------------------
extern "C" void kernel_launch(void* const* d_in, const int* in_sizes, int n_in,
                              void* d_out, int out_size) {
    (void)in_sizes; (void)n_in; (void)out_size;
    const float* x   = (const float*)d_in[0];
    const int* pos   = (const int*)d_in[1];
    const float* Wq  = (const float*)d_in[3];
    const float* Wk  = (const float*)d_in[4];
    const float* Wv  = (const float*)d_in[5];
    const float* Wo  = (const float*)d_in[6];
    const float* qns = (const float*)d_in[7];
    const float* kns = (const float*)d_in[8];
    float* out = (float*)d_out;

    __half *xh, *wqh, *wkvh, *woh, *qh, *kh, *vh, *ctxh;
    float *qraw, *kvraw;
    cudaGetSymbolAddress((void**)&xh,   g_xh);
    cudaGetSymbolAddress((void**)&wqh,  g_wqh);
    cudaGetSymbolAddress((void**)&wkvh, g_wkvh);
    cudaGetSymbolAddress((void**)&woh,  g_woh);
    cudaGetSymbolAddress((void**)&qraw, g_q_raw);
    cudaGetSymbolAddress((void**)&kvraw, g_kv_raw);
    cudaGetSymbolAddress((void**)&qh, g_qh);
    cudaGetSymbolAddress((void**)&kh, g_kh);
    cudaGetSymbolAddress((void**)&vh, g_vh);
    cudaGetSymbolAddress((void**)&ctxh, g_ctxh);

    cudaFuncSetAttribute(sgemm_h,
                         cudaFuncAttributeMaxDynamicSharedMemorySize, GEMM_SMEM);
    cudaFuncSetAttribute(attn_mma2,
                         cudaFuncAttributeMaxDynamicSharedMemorySize, AT_SMEM);

    // 1. fp16 converts + rope table (ILP-4 kernels)
    cvt_h<<<BS_ * 2048 / 4 / 1024, 256>>>(x, xh, BS_ * 2048 / 4);
    cvt_h<<<2048 * 2048 / 4 / 1024, 256>>>(Wq, wqh, 2048 * 2048 / 4);
    cvt_kv<<<2048 * 1024 / 4 / 1024, 256>>>(Wk, Wv);
    cvt_h<<<2048 * 2048 / 4 / 1024, 256>>>(Wo, woh, 2048 * 2048 / 4);
    rope_table_kernel<<<BS_ * 64 / 256, 256>>>(pos);

    // 2. Q and fused K|V projections (fp16 mma)
    sgemm_h<<<dim3(2048 / 128, BS_ / 128), 256, GEMM_SMEM>>>(xh, wqh, qraw, 2048, 2048);
    sgemm_h<<<dim3(1024 / 128, BS_ / 128), 256, GEMM_SMEM>>>(xh, wkvh, kvraw, 1024, 2048);

    // 3. RMSNorm + RoPE + fp16
    {
        dim3 g(BS_, 24);
        normrope_kernel<<<g, 128>>>(qns, kns);
    }
    // 4. Attention
    {
        dim3 g(S_ / 128, B_ * H_);
        attn_mma2<<<g, 256, AT_SMEM>>>(qh, kh, vh, ctxh);
    }
    // 5. Output projection
    sgemm_h<<<dim3(2048 / 128, BS_ / 128), 256, GEMM_SMEM>>>(ctxh, woh, out, 2048, 2048);
}